// round 13
// baseline (speedup 1.0000x reference)
#include <cuda_runtime.h>
#include <cuda_fp16.h>
#include <cstdint>

#define BB 512
#define THIST 512
#define HENC 256
#define HH 256
#define AA 256
#define TPRED 32
#define NG 1024
#define NCTAS 128

// ---------------- device scratch (static only) ----------------
__device__ __half g_ep_h[(size_t)BB * THIST * AA];    // enc_proj fp16
__device__ __half g_eo_h[(size_t)BB * THIST * HENC];  // encoder_outputs fp16
__device__ __half g_Wt_ench[HENC * AA];               // [a][e] fp16
__device__ __half g_Wcat0rh[NG * 512];                // gate-interleaved n'=4j+g
__device__ __half g_Wcat1rh[NG * 512];
__device__ __half g_Wfc1h[HH * 512];
__device__ __half g_Wt_dech[AA * HH];                 // [a][h]
__device__ float g_wcol0r[NG];
__device__ float g_bias0r[NG];
__device__ float g_bias1r[NG];
__device__ float g_h0[BB * HH], g_h1[BB * HH];
__device__ float g_c0[BB * HH], g_c1[BB * HH];
__device__ float g_dec_in[BB];
__device__ float g_dp[BB * AA];
__device__ float g_fcp4[BB * 4];
__device__ __half g_xcat0h[BB * 512];                 // [ctx | h0_old]
__device__ __half g_xcat1h[BB * 512];                 // [h0_new | h1_old]
__device__ __half g_xcatfch[BB * 512];                // [h1_new | ctx]

__device__ unsigned g_count = 0;
__device__ unsigned g_sense = 0;

// ---------------- helpers ----------------
__device__ __forceinline__ float ftanh_fast(float x) {
    float y;
    asm("tanh.approx.f32 %0, %1;" : "=f"(y) : "f"(x));
    return y;
}
__device__ __forceinline__ float sig_precise(float x) { return 1.f / (1.f + expf(-x)); }

__device__ __forceinline__ uint32_t smem_u32(const void* p) {
    uint32_t a;
    asm("{.reg .u64 t; cvta.to.shared.u64 t, %1; cvt.u32.u64 %0, t;}" : "=r"(a) : "l"(p));
    return a;
}
__device__ __forceinline__ void ldsm_x4(uint32_t addr, uint32_t& r0, uint32_t& r1,
                                        uint32_t& r2, uint32_t& r3) {
    asm volatile("ldmatrix.sync.aligned.m8n8.x4.shared.b16 {%0,%1,%2,%3}, [%4];"
                 : "=r"(r0), "=r"(r1), "=r"(r2), "=r"(r3) : "r"(addr));
}
__device__ __forceinline__ void mma16816(float* d, uint32_t a0, uint32_t a1, uint32_t a2,
                                         uint32_t a3, uint32_t b0, uint32_t b1) {
    asm volatile(
        "mma.sync.aligned.m16n8k16.row.col.f32.f16.f16.f32 "
        "{%0,%1,%2,%3},{%4,%5,%6,%7},{%8,%9},{%0,%1,%2,%3};"
        : "+f"(d[0]), "+f"(d[1]), "+f"(d[2]), "+f"(d[3])
        : "r"(a0), "r"(a1), "r"(a2), "r"(a3), "r"(b0), "r"(b1));
}
__device__ __forceinline__ int4 ldcs_int4(const void* p) {
    int4 v;
    asm volatile("ld.global.cs.v4.b32 {%0,%1,%2,%3}, [%4];"
                 : "=r"(v.x), "=r"(v.y), "=r"(v.z), "=r"(v.w) : "l"(p));
    return v;
}

__device__ __forceinline__ void grid_barrier(unsigned* eps) {
    __syncthreads();
    if (threadIdx.x == 0) {
        unsigned target = ++(*eps);
        __threadfence();
        unsigned old = atomicAdd(&g_count, 1);
        if (old == NCTAS - 1) {
            g_count = 0;
            __threadfence();
            atomicExch(&g_sense, target);
        } else {
            while (atomicAdd(&g_sense, 0) != target) __nanosleep(64);
        }
    }
    __syncthreads();
}

// ---------------- init + prep ----------------
__global__ void init_state(const float* __restrict__ eh, const float* __restrict__ ec) {
    int i = blockIdx.x * blockDim.x + threadIdx.x;
    if (i < BB * HH) {
        g_h0[i] = eh[i];
        g_h1[i] = eh[BB * HH + i];
        g_c0[i] = ec[i];
        g_c1[i] = ec[BB * HH + i];
    }
    if (i < BB) g_dec_in[i] = 0.f;
}

__global__ void prep(const float* __restrict__ Wae, const float* __restrict__ Wad,
                     const float* __restrict__ Wih0, const float* __restrict__ Whh0,
                     const float* __restrict__ bih0, const float* __restrict__ bhh0,
                     const float* __restrict__ Wih1, const float* __restrict__ Whh1,
                     const float* __restrict__ bih1, const float* __restrict__ bhh1,
                     const float* __restrict__ Wfc1) {
    int i = blockIdx.x * blockDim.x + threadIdx.x;
    if (i < HENC * AA) {
        int a = i / HENC, e = i % HENC;
        g_Wt_ench[i] = __float2half(Wae[e * AA + a]);
    }
    if (i < NG * 512) {
        int n4 = i >> 9, c = i & 511;
        int j = n4 >> 2, g = n4 & 3;
        int n = g * 256 + j;
        g_Wcat0rh[i] = __float2half((c < 256) ? Wih0[n * 257 + 1 + c] : Whh0[n * 256 + (c - 256)]);
        g_Wcat1rh[i] = __float2half((c < 256) ? Wih1[n * 256 + c] : Whh1[n * 256 + (c - 256)]);
    }
    if (i < HH * 512) g_Wfc1h[i] = __float2half(Wfc1[i]);
    if (i < AA * HH) {
        int a = i >> 8, h = i & 255;
        g_Wt_dech[i] = __float2half(Wad[h * AA + a]);
    }
    if (i < NG) {
        int j = i >> 2, g = i & 3;
        int n = g * 256 + j;
        g_wcol0r[i] = Wih0[n * 257];
        g_bias0r[i] = bih0[n] + bhh0[n];
        g_bias1r[i] = bih1[n] + bhh1[n];
    }
}

__global__ void prep_eo(const float* __restrict__ eo) {
    int i = blockIdx.x * blockDim.x + threadIdx.x;
    const float4 v = ((const float4*)eo)[i];
    __half2 h[2] = {__floats2half2_rn(v.x, v.y), __floats2half2_rn(v.z, v.w)};
    ((uint2*)g_eo_h)[i] = *(uint2*)h;
}

// ---------------- enc_proj: single fp16 MMA, 128x64 tile, double-buffered ----------------
// warp grid 4(m) x 2(n). B loaded via ldsm.x4: 2 n-tiles x 2 k-halves per op.
__global__ __launch_bounds__(256) void encproj_mma() {
    __shared__ __half sA[2][128 * 40], sB[2][64 * 40];
    const int m0 = blockIdx.y * 128;
    const int n0 = blockIdx.x * 64;
    const int tid = threadIdx.x, lane = tid & 31, wid = tid >> 5;
    const int wm = wid & 3, wn = wid >> 2;
    float cf[2][4][4];
#pragma unroll
    for (int mt = 0; mt < 2; mt++)
#pragma unroll
        for (int nt = 0; nt < 4; nt++)
#pragma unroll
            for (int q = 0; q < 4; q++) cf[mt][nt][q] = 0.f;
    const int aRow = tid >> 1, aCol = (tid & 1) * 8;
    const int bRow = tid >> 2, bCol = (tid & 3) * 8;
    const uint32_t aB = smem_u32(sA), bB = smem_u32(sB);
    const int arow = wm * 32 + (lane & 15);
    const int acol8 = 8 * (lane >> 4);
    // B x4 lane mapping: p=lane>>3 -> (nt offset p>>1, k-half p&1)
    const int bxrow = 8 * (lane >> 4) + (lane & 7);      // within 16-row pair
    const int bxcol8 = 8 * ((lane >> 3) & 1);

    uint4 ra0 = *(const uint4*)&g_eo_h[(size_t)(m0 + aRow) * 256 + aCol];
    uint4 ra1 = *(const uint4*)&g_eo_h[(size_t)(m0 + aRow) * 256 + aCol + 16];
    uint4 rb = *(const uint4*)&g_Wt_ench[(size_t)(n0 + bRow) * 256 + bCol];
#pragma unroll
    for (int it = 0; it < 8; it++) {
        const int buf = it & 1;
        *(uint4*)&sA[buf][aRow * 40 + aCol] = ra0;
        *(uint4*)&sA[buf][aRow * 40 + aCol + 16] = ra1;
        *(uint4*)&sB[buf][bRow * 40 + bCol] = rb;
        __syncthreads();
        if (it < 7) {
            const int kc = (it + 1) * 32;
            ra0 = *(const uint4*)&g_eo_h[(size_t)(m0 + aRow) * 256 + kc + aCol];
            ra1 = *(const uint4*)&g_eo_h[(size_t)(m0 + aRow) * 256 + kc + aCol + 16];
            rb = *(const uint4*)&g_Wt_ench[(size_t)(n0 + bRow) * 256 + kc + bCol];
        }
        const uint32_t offA = buf * (128 * 40) * 2;
        const uint32_t offB = buf * (64 * 40) * 2;
#pragma unroll
        for (int ks = 0; ks < 32; ks += 16) {
            uint32_t a[2][4], b[4][2];
#pragma unroll
            for (int mt = 0; mt < 2; mt++)
                ldsm_x4(aB + offA + ((arow + mt * 16) * 40 + ks + acol8) * 2,
                        a[mt][0], a[mt][1], a[mt][2], a[mt][3]);
#pragma unroll
            for (int q = 0; q < 2; q++) {
                // covers n-tiles 2q, 2q+1 (rows wn*32 + q*16 .. +15), both k-halves
                ldsm_x4(bB + offB + ((wn * 32 + q * 16 + bxrow) * 40 + ks + bxcol8) * 2,
                        b[2 * q][0], b[2 * q][1], b[2 * q + 1][0], b[2 * q + 1][1]);
            }
#pragma unroll
            for (int mt = 0; mt < 2; mt++)
#pragma unroll
                for (int nt = 0; nt < 4; nt++)
                    mma16816(cf[mt][nt], a[mt][0], a[mt][1], a[mt][2], a[mt][3],
                             b[nt][0], b[nt][1]);
        }
    }
    const int erow = wm * 32 + (lane >> 2);
    const int ecol0 = wn * 32 + (lane & 3) * 2;
#pragma unroll
    for (int mt = 0; mt < 2; mt++)
#pragma unroll
        for (int nt = 0; nt < 4; nt++) {
            int r = m0 + erow + mt * 16, c = n0 + ecol0 + nt * 8;
            *(__half2*)&g_ep_h[(size_t)r * AA + c] = __floats2half2_rn(cf[mt][nt][0], cf[mt][nt][1]);
            *(__half2*)&g_ep_h[(size_t)(r + 8) * AA + c] = __floats2half2_rn(cf[mt][nt][2], cf[mt][nt][3]);
        }
}

// ---------------- fused attention (per step) + prev-step fc2 finalize ----------------
__global__ __launch_bounds__(256) void attn_step(const float* __restrict__ v,
                                                 float* __restrict__ attn_out,
                                                 const float* __restrict__ bfc2,
                                                 float* __restrict__ outs, int s) {
    __shared__ float s_dp[256];
    __shared__ float s_v[256];
    __shared__ float s_sc[512];
    __shared__ float s_red[8];
    __shared__ float s_ctx[8][256];
    const int b = blockIdx.x;
    const int tid = threadIdx.x;
    const int lane = tid & 31, w = tid >> 5;

    if (s > 0 && tid == 0) {
        const float4 p = *(const float4*)&g_fcp4[b * 4];
        float o = (p.x + p.y) + (p.z + p.w) + bfc2[0];
        outs[b * TPRED + (s - 1)] = o;
        g_dec_in[b] = o;
    }

    s_dp[tid] = g_dp[b * 256 + tid];
    s_v[tid] = v[tid];
    __syncthreads();

    float vr[8], dr[8];
#pragma unroll
    for (int i = 0; i < 8; i++) {
        vr[i] = s_v[lane * 8 + i];
        dr[i] = s_dp[lane * 8 + i];
    }

    const __half* ep = g_ep_h + (size_t)b * THIST * AA;
    for (int i0 = 0; i0 < 64; i0 += 8) {
        int4 raw[8];
#pragma unroll
        for (int u = 0; u < 8; u++) {
            int t = w + (i0 + u) * 8;
            raw[u] = ldcs_int4(ep + (size_t)t * AA + lane * 8);
        }
        float ss[8];
#pragma unroll
        for (int u = 0; u < 8; u++) {
            const __half2* hp = (const __half2*)&raw[u];
            float acc = 0.f;
#pragma unroll
            for (int q = 0; q < 4; q++) {
                float2 f = __half22float2(hp[q]);
                acc = fmaf(vr[2 * q + 0], ftanh_fast(f.x + dr[2 * q + 0]), acc);
                acc = fmaf(vr[2 * q + 1], ftanh_fast(f.y + dr[2 * q + 1]), acc);
            }
            ss[u] = acc;
        }
#pragma unroll
        for (int off = 16; off; off >>= 1)
#pragma unroll
            for (int u = 0; u < 8; u++) ss[u] += __shfl_xor_sync(0xffffffffu, ss[u], off);
        if (lane == 0) {
#pragma unroll
            for (int u = 0; u < 8; u++) s_sc[w + (i0 + u) * 8] = ss[u];
        }
    }
    __syncthreads();

    float m = fmaxf(s_sc[tid], s_sc[tid + 256]);
#pragma unroll
    for (int off = 16; off; off >>= 1) m = fmaxf(m, __shfl_xor_sync(0xffffffffu, m, off));
    if (lane == 0) s_red[w] = m;
    __syncthreads();
    float mm = s_red[0];
#pragma unroll
    for (int i = 1; i < 8; i++) mm = fmaxf(mm, s_red[i]);
    float e0 = __expf(s_sc[tid] - mm);
    float e1 = __expf(s_sc[tid + 256] - mm);
    float sm = e0 + e1;
#pragma unroll
    for (int off = 16; off; off >>= 1) sm += __shfl_xor_sync(0xffffffffu, sm, off);
    __syncthreads();
    if (lane == 0) s_red[w] = sm;
    __syncthreads();
    float tot = s_red[0];
#pragma unroll
    for (int i = 1; i < 8; i++) tot += s_red[i];
    float inv = 1.f / tot;
    float p0 = e0 * inv, p1 = e1 * inv;
    s_sc[tid] = p0;
    s_sc[tid + 256] = p1;
    attn_out[(size_t)b * THIST + tid] = p0;
    attn_out[(size_t)b * THIST + tid + 256] = p1;
    __syncthreads();

    const __half* eob = g_eo_h + (size_t)b * THIST * HENC;
    float cacc[8];
#pragma unroll
    for (int q = 0; q < 8; q++) cacc[q] = 0.f;
    for (int i0 = 0; i0 < 64; i0 += 8) {
        int4 r[8];
        float p[8];
#pragma unroll
        for (int u = 0; u < 8; u++) {
            int t = w + (i0 + u) * 8;
            r[u] = ldcs_int4(eob + (size_t)t * HENC + lane * 8);
            p[u] = s_sc[t];
        }
#pragma unroll
        for (int u = 0; u < 8; u++) {
            const __half2* hp = (const __half2*)&r[u];
#pragma unroll
            for (int q = 0; q < 4; q++) {
                float2 f = __half22float2(hp[q]);
                cacc[2 * q + 0] = fmaf(p[u], f.x, cacc[2 * q + 0]);
                cacc[2 * q + 1] = fmaf(p[u], f.y, cacc[2 * q + 1]);
            }
        }
    }
#pragma unroll
    for (int q = 0; q < 8; q++) s_ctx[w][lane * 8 + q] = cacc[q];
    __syncthreads();

    const int e = tid;
    float csum = 0.f;
#pragma unroll
    for (int q = 0; q < 8; q++) csum += s_ctx[q][e];
    g_xcat0h[b * 512 + e] = __float2half(csum);
    g_xcat0h[b * 512 + 256 + e] = __float2half(g_h0[b * 256 + e]);
    g_xcatfch[b * 512 + 256 + e] = __float2half(csum);
}

// ---------------- double-buffered fp16 MMA 64x64 tile GEMM core ----------------
__device__ void gemm_mma_db(const __half* __restrict__ A, int lda,
                            const __half* __restrict__ B, int ldb,
                            int m0, int n0, int ktot, float cf[2][2][4]) {
    static __shared__ __half sA[2][64 * 40];
    static __shared__ __half sB[2][64 * 40];
    const int tid = threadIdx.x, lane = tid & 31, wid = tid >> 5;
    const int wm = wid & 1, wn = wid >> 1;
#pragma unroll
    for (int mt = 0; mt < 2; mt++)
#pragma unroll
        for (int nt = 0; nt < 2; nt++)
#pragma unroll
            for (int q = 0; q < 4; q++) cf[mt][nt][q] = 0.f;
    const int lrow = tid >> 2, lcol = (tid & 3) * 8;
    const uint32_t aBase = smem_u32(sA), bBase = smem_u32(sB);
    const int arow = wm * 32 + (lane & 15);
    const int acol8 = 8 * (lane >> 4);
    const int bxrow = 8 * (lane >> 4) + (lane & 7);   // x4 B mapping
    const int bxcol8 = 8 * ((lane >> 3) & 1);
    const int niter = ktot / 32;

    uint4 ra = *(const uint4*)&A[(size_t)(m0 + lrow) * lda + lcol];
    uint4 rb = *(const uint4*)&B[(size_t)(n0 + lrow) * ldb + lcol];
    for (int it = 0; it < niter; it++) {
        const int buf = it & 1;
        *(uint4*)&sA[buf][lrow * 40 + lcol] = ra;
        *(uint4*)&sB[buf][lrow * 40 + lcol] = rb;
        __syncthreads();
        if (it + 1 < niter) {
            const int kc = (it + 1) * 32;
            ra = *(const uint4*)&A[(size_t)(m0 + lrow) * lda + kc + lcol];
            rb = *(const uint4*)&B[(size_t)(n0 + lrow) * ldb + kc + lcol];
        }
        const uint32_t off = buf * (64 * 40) * 2;
#pragma unroll
        for (int ks = 0; ks < 32; ks += 16) {
            uint32_t a[2][4], bfrag[2][2];
#pragma unroll
            for (int mt = 0; mt < 2; mt++)
                ldsm_x4(aBase + off + ((arow + mt * 16) * 40 + ks + acol8) * 2,
                        a[mt][0], a[mt][1], a[mt][2], a[mt][3]);
            // one x4 covers both n-tiles (16 rows at wn*16) x 2 k-halves
            ldsm_x4(bBase + off + ((wn * 16 + bxrow) * 40 + ks + bxcol8) * 2,
                    bfrag[0][0], bfrag[0][1], bfrag[1][0], bfrag[1][1]);
#pragma unroll
            for (int mt = 0; mt < 2; mt++)
#pragma unroll
                for (int nt = 0; nt < 2; nt++)
                    mma16816(cf[mt][nt], a[mt][0], a[mt][1], a[mt][2], a[mt][3],
                             bfrag[nt][0], bfrag[nt][1]);
        }
    }
}

// ---------------- fused recurrent step: 3 phases, 2 barriers ----------------
__global__ __launch_bounds__(256) void recurrent_step(const float* __restrict__ bfc1,
                                                      const float* __restrict__ Wfc2) {
    unsigned eps = 0;
    if (threadIdx.x == 0) eps = atomicAdd(&g_sense, 0);
    const int cta = blockIdx.x;
    const int tid = threadIdx.x;
    const int lane = tid & 31, wid = tid >> 5;
    const int wm = wid & 1, wn = wid >> 1;
    const int parity = lane & 1;
    float cf[2][2][4];

    // ===== P0: lstm0 gates GEMM + cell0 epilogue =====
    {
        const int m0 = (cta & 7) * 64, n0 = (cta >> 3) * 64;
        gemm_mma_db(g_xcat0h, 512, g_Wcat0rh, 512, m0, n0, 512, cf);
#pragma unroll
        for (int mt = 0; mt < 2; mt++)
#pragma unroll
            for (int nt = 0; nt < 2; nt++) {
                float t0 = __shfl_xor_sync(0xffffffffu, cf[mt][nt][0], 1);
                float t1 = __shfl_xor_sync(0xffffffffu, cf[mt][nt][1], 1);
                float t2 = __shfl_xor_sync(0xffffffffu, cf[mt][nt][2], 1);
                float t3 = __shfl_xor_sync(0xffffffffu, cf[mt][nt][3], 1);
                const int c = n0 + wn * 16 + (lane & 3) * 2 + nt * 8;
                const int j = c >> 2;
                const int r = m0 + wm * 32 + (lane >> 2) + mt * 16;
                int b;
                float gi, gf, gg, go;
                if (!parity) { b = r;     gi = cf[mt][nt][0]; gf = cf[mt][nt][1]; gg = t0; go = t1; }
                else         { b = r + 8; gi = t2;            gf = t3;            gg = cf[mt][nt][2]; go = cf[mt][nt][3]; }
                const float din = g_dec_in[b];
                const float4 wc = *(const float4*)&g_wcol0r[4 * j];
                const float4 bs = *(const float4*)&g_bias0r[4 * j];
                gi += din * wc.x + bs.x;
                gf += din * wc.y + bs.y;
                gg += din * wc.z + bs.z;
                go += din * wc.w + bs.w;
                const int idx = b * 256 + j;
                float cc = sig_precise(gf) * g_c0[idx] + sig_precise(gi) * tanhf(gg);
                float hh = sig_precise(go) * tanhf(cc);
                g_c0[idx] = cc;
                g_h0[idx] = hh;
                g_xcat1h[b * 512 + j] = __float2half(hh);
                g_xcat1h[b * 512 + 256 + j] = __float2half(g_h1[idx]);
            }
    }
    grid_barrier(&eps);

    // ===== P1: lstm1 gates GEMM + cell1 epilogue =====
    {
        const int m0 = (cta & 7) * 64, n0 = (cta >> 3) * 64;
        gemm_mma_db(g_xcat1h, 512, g_Wcat1rh, 512, m0, n0, 512, cf);
#pragma unroll
        for (int mt = 0; mt < 2; mt++)
#pragma unroll
            for (int nt = 0; nt < 2; nt++) {
                float t0 = __shfl_xor_sync(0xffffffffu, cf[mt][nt][0], 1);
                float t1 = __shfl_xor_sync(0xffffffffu, cf[mt][nt][1], 1);
                float t2 = __shfl_xor_sync(0xffffffffu, cf[mt][nt][2], 1);
                float t3 = __shfl_xor_sync(0xffffffffu, cf[mt][nt][3], 1);
                const int c = n0 + wn * 16 + (lane & 3) * 2 + nt * 8;
                const int j = c >> 2;
                const int r = m0 + wm * 32 + (lane >> 2) + mt * 16;
                int b;
                float gi, gf, gg, go;
                if (!parity) { b = r;     gi = cf[mt][nt][0]; gf = cf[mt][nt][1]; gg = t0; go = t1; }
                else         { b = r + 8; gi = t2;            gf = t3;            gg = cf[mt][nt][2]; go = cf[mt][nt][3]; }
                const float4 bs = *(const float4*)&g_bias1r[4 * j];
                gi += bs.x;
                gf += bs.y;
                gg += bs.z;
                go += bs.w;
                const int idx = b * 256 + j;
                float cc = sig_precise(gf) * g_c1[idx] + sig_precise(gi) * tanhf(gg);
                float hh = sig_precise(go) * tanhf(cc);
                g_c1[idx] = cc;
                g_h1[idx] = hh;
                g_xcatfch[b * 512 + j] = __float2half(hh);
            }
    }
    grid_barrier(&eps);

    // ===== P2: fc1+relu+Wfc2 partial (ctas 0-31) | dec_proj (ctas 32-63) =====
    if (cta < 32) {
        __shared__ float sfc[64][4];
        const int m0 = (cta & 7) * 64, n0 = (cta >> 3) * 64;
        gemm_mma_db(g_xcatfch, 512, g_Wfc1h, 512, m0, n0, 512, cf);
        float s0[2] = {0.f, 0.f}, s1[2] = {0.f, 0.f};
#pragma unroll
        for (int mt = 0; mt < 2; mt++)
#pragma unroll
            for (int nt = 0; nt < 2; nt++) {
                const int c = n0 + wn * 16 + (lane & 3) * 2 + nt * 8;
                const float b0 = bfc1[c], b1 = bfc1[c + 1];
                const float w0 = Wfc2[c], w1 = Wfc2[c + 1];
                s0[mt] += fmaxf(cf[mt][nt][0] + b0, 0.f) * w0 + fmaxf(cf[mt][nt][1] + b1, 0.f) * w1;
                s1[mt] += fmaxf(cf[mt][nt][2] + b0, 0.f) * w0 + fmaxf(cf[mt][nt][3] + b1, 0.f) * w1;
            }
#pragma unroll
        for (int off = 1; off < 4; off <<= 1) {
#pragma unroll
            for (int mt = 0; mt < 2; mt++) {
                s0[mt] += __shfl_xor_sync(0xffffffffu, s0[mt], off);
                s1[mt] += __shfl_xor_sync(0xffffffffu, s1[mt], off);
            }
        }
        if ((lane & 3) == 0) {
#pragma unroll
            for (int mt = 0; mt < 2; mt++) {
                int rl = wm * 32 + (lane >> 2) + mt * 16;
                sfc[rl][wn] = s0[mt];
                sfc[rl + 8][wn] = s1[mt];
            }
        }
        __syncthreads();
        if (tid < 64) {
            float p = sfc[tid][0] + sfc[tid][1] + sfc[tid][2] + sfc[tid][3];
            g_fcp4[(m0 + tid) * 4 + (cta >> 3)] = p;
        }
    } else if (cta < 64) {
        const int c2 = cta - 32;
        const int m0 = (c2 & 7) * 64, n0 = (c2 >> 3) * 64;
        gemm_mma_db(g_xcatfch, 512, g_Wt_dech, 256, m0, n0, 256, cf);
        const int erow = wm * 32 + (lane >> 2);
        const int ecol = wn * 16 + (lane & 3) * 2;
#pragma unroll
        for (int mt = 0; mt < 2; mt++)
#pragma unroll
            for (int nt = 0; nt < 2; nt++) {
                int r = m0 + erow + mt * 16, c = n0 + ecol + nt * 8;
                *(float2*)&g_dp[(size_t)r * AA + c] = make_float2(cf[mt][nt][0], cf[mt][nt][1]);
                *(float2*)&g_dp[(size_t)(r + 8) * AA + c] = make_float2(cf[mt][nt][2], cf[mt][nt][3]);
            }
    }
}

// ---------------- finalize last step's fc output ----------------
__global__ void finalize(const float* __restrict__ bfc2, float* __restrict__ outs) {
    int b = blockIdx.x * 256 + threadIdx.x;
    const float4 p = *(const float4*)&g_fcp4[b * 4];
    outs[b * TPRED + (TPRED - 1)] = (p.x + p.y) + (p.z + p.w) + bfc2[0];
}

// ---------------- initial dec_proj from encoder_hidden[1] ----------------
__global__ __launch_bounds__(256) void dp_init(const float* __restrict__ Wad) {
    __shared__ float sA[8][256];
    const int b0 = blockIdx.x * 8;
    const int tid = threadIdx.x;
#pragma unroll
    for (int q = 0; q < 2; q++) {
        int f4 = q * 256 + tid;
        int r = f4 >> 6, c = (f4 & 63) * 4;
        *(float4*)&sA[r][c] = *(const float4*)&g_h1[(size_t)(b0 + r) * 256 + c];
    }
    __syncthreads();
    float dpa[8];
#pragma unroll
    for (int r = 0; r < 8; r++) dpa[r] = 0.f;
#pragma unroll 4
    for (int h = 0; h < 256; h++) {
        const float wv = Wad[(size_t)h * AA + tid];
#pragma unroll
        for (int r = 0; r < 8; r++) dpa[r] = fmaf(sA[r][h], wv, dpa[r]);
    }
#pragma unroll
    for (int r = 0; r < 8; r++) g_dp[(b0 + r) * 256 + tid] = dpa[r];
}

// ---------------- host launcher ----------------
extern "C" void kernel_launch(void* const* d_in, const int* in_sizes, int n_in,
                              void* d_out, int out_size) {
    int off = (in_sizes[0] == 1) ? 1 : 0;
    const float* enc_out = (const float*)d_in[off + 0];
    const float* enc_h = (const float*)d_in[off + 1];
    const float* enc_c = (const float*)d_in[off + 2];
    const float* Wae = (const float*)d_in[off + 3];
    const float* Wad = (const float*)d_in[off + 4];
    const float* v = (const float*)d_in[off + 5];
    const float* Wih0 = (const float*)d_in[off + 6];
    const float* Whh0 = (const float*)d_in[off + 7];
    const float* bih0 = (const float*)d_in[off + 8];
    const float* bhh0 = (const float*)d_in[off + 9];
    const float* Wih1 = (const float*)d_in[off + 10];
    const float* Whh1 = (const float*)d_in[off + 11];
    const float* bih1 = (const float*)d_in[off + 12];
    const float* bhh1 = (const float*)d_in[off + 13];
    const float* Wfc1 = (const float*)d_in[off + 14];
    const float* bfc1 = (const float*)d_in[off + 15];
    const float* Wfc2 = (const float*)d_in[off + 16];
    const float* bfc2 = (const float*)d_in[off + 17];

    float* out = (float*)d_out;
    float* attn_base = out + (size_t)BB * TPRED;

    init_state<<<(BB * HH + 255) / 256, 256>>>(enc_h, enc_c);
    prep<<<2048, 256>>>(Wae, Wad, Wih0, Whh0, bih0, bhh0, Wih1, Whh1, bih1, bhh1, Wfc1);
    prep_eo<<<(BB * THIST * HENC / 4) / 256, 256>>>(enc_out);
    encproj_mma<<<dim3(4, 2048), 256>>>();
    dp_init<<<BB / 8, 256>>>(Wad);

    for (int s = 0; s < TPRED; s++) {
        attn_step<<<BB, 256>>>(v, attn_base + (size_t)s * BB * THIST, bfc2, out, s);
        recurrent_step<<<NCTAS, 256>>>(bfc1, Wfc2);
    }
    finalize<<<2, 256>>>(bfc2, out);
    (void)n_in;
    (void)out_size;
}

// round 14
// speedup vs baseline: 1.0614x; 1.0614x over previous
#include <cuda_runtime.h>
#include <cuda_fp16.h>
#include <cstdint>

#define BB 512
#define THIST 512
#define HENC 256
#define HH 256
#define AA 256
#define TPRED 32
#define NG 1024
#define NCTAS 128

// ---------------- device scratch (static only) ----------------
__device__ __half g_ep_h[(size_t)BB * THIST * AA];
__device__ __half g_eo_h[(size_t)BB * THIST * HENC];
__device__ __half g_Wt_ench[HENC * AA];
__device__ __half g_Wcat0rh[NG * 512];
__device__ __half g_Wcat1rh[NG * 512];
__device__ __half g_Wfc1h[HH * 512];
__device__ __half g_Wt_dech[AA * HH];
__device__ float g_wcol0r[NG];
__device__ float g_bias0r[NG];
__device__ float g_bias1r[NG];
__device__ float g_h0[BB * HH], g_h1[BB * HH];
__device__ float g_c0[BB * HH], g_c1[BB * HH];
__device__ float g_dec_in[BB];
__device__ float g_dp[BB * AA];
__device__ float g_fcp4[BB * 4];
__device__ __half g_xcat0h[BB * 512];
__device__ __half g_xcat1h[BB * 512];
__device__ __half g_xcatfch[BB * 512];

__device__ unsigned g_count = 0;
__device__ unsigned g_sense = 0;

// ---------------- helpers ----------------
__device__ __forceinline__ float ftanh_fast(float x) {
    float y;
    asm("tanh.approx.f32 %0, %1;" : "=f"(y) : "f"(x));
    return y;
}
__device__ __forceinline__ float sig_precise(float x) { return 1.f / (1.f + expf(-x)); }

__device__ __forceinline__ uint32_t smem_u32(const void* p) {
    uint32_t a;
    asm("{.reg .u64 t; cvta.to.shared.u64 t, %1; cvt.u32.u64 %0, t;}" : "=r"(a) : "l"(p));
    return a;
}
__device__ __forceinline__ void ldsm_x4(uint32_t addr, uint32_t& r0, uint32_t& r1,
                                        uint32_t& r2, uint32_t& r3) {
    asm volatile("ldmatrix.sync.aligned.m8n8.x4.shared.b16 {%0,%1,%2,%3}, [%4];"
                 : "=r"(r0), "=r"(r1), "=r"(r2), "=r"(r3) : "r"(addr));
}
__device__ __forceinline__ void ldsm_x2(uint32_t addr, uint32_t& r0, uint32_t& r1) {
    asm volatile("ldmatrix.sync.aligned.m8n8.x2.shared.b16 {%0,%1}, [%2];"
                 : "=r"(r0), "=r"(r1) : "r"(addr));
}
__device__ __forceinline__ void mma16816(float* d, uint32_t a0, uint32_t a1, uint32_t a2,
                                         uint32_t a3, uint32_t b0, uint32_t b1) {
    asm volatile(
        "mma.sync.aligned.m16n8k16.row.col.f32.f16.f16.f32 "
        "{%0,%1,%2,%3},{%4,%5,%6,%7},{%8,%9},{%0,%1,%2,%3};"
        : "+f"(d[0]), "+f"(d[1]), "+f"(d[2]), "+f"(d[3])
        : "r"(a0), "r"(a1), "r"(a2), "r"(a3), "r"(b0), "r"(b1));
}
__device__ __forceinline__ int4 ldcs_int4(const void* p) {
    int4 v;
    asm volatile("ld.global.cs.v4.b32 {%0,%1,%2,%3}, [%4];"
                 : "=r"(v.x), "=r"(v.y), "=r"(v.z), "=r"(v.w) : "l"(p));
    return v;
}

__device__ __forceinline__ void grid_barrier(unsigned* eps) {
    __syncthreads();
    if (threadIdx.x == 0) {
        unsigned target = ++(*eps);
        __threadfence();
        unsigned old = atomicAdd(&g_count, 1);
        if (old == NCTAS - 1) {
            g_count = 0;
            __threadfence();
            atomicExch(&g_sense, target);
        } else {
            while (atomicAdd(&g_sense, 0) != target) __nanosleep(64);
        }
    }
    __syncthreads();
}

// ---------------- init + prep ----------------
__global__ void init_state(const float* __restrict__ eh, const float* __restrict__ ec) {
    int i = blockIdx.x * blockDim.x + threadIdx.x;
    if (i < BB * HH) {
        g_h0[i] = eh[i];
        g_h1[i] = eh[BB * HH + i];
        g_c0[i] = ec[i];
        g_c1[i] = ec[BB * HH + i];
    }
    if (i < BB) g_dec_in[i] = 0.f;
}

__global__ void prep(const float* __restrict__ Wae, const float* __restrict__ Wad,
                     const float* __restrict__ Wih0, const float* __restrict__ Whh0,
                     const float* __restrict__ bih0, const float* __restrict__ bhh0,
                     const float* __restrict__ Wih1, const float* __restrict__ Whh1,
                     const float* __restrict__ bih1, const float* __restrict__ bhh1,
                     const float* __restrict__ Wfc1) {
    int i = blockIdx.x * blockDim.x + threadIdx.x;
    if (i < HENC * AA) {
        int a = i / HENC, e = i % HENC;
        g_Wt_ench[i] = __float2half(Wae[e * AA + a]);
    }
    if (i < NG * 512) {
        int n4 = i >> 9, c = i & 511;
        int j = n4 >> 2, g = n4 & 3;
        int n = g * 256 + j;
        g_Wcat0rh[i] = __float2half((c < 256) ? Wih0[n * 257 + 1 + c] : Whh0[n * 256 + (c - 256)]);
        g_Wcat1rh[i] = __float2half((c < 256) ? Wih1[n * 256 + c] : Whh1[n * 256 + (c - 256)]);
    }
    if (i < HH * 512) g_Wfc1h[i] = __float2half(Wfc1[i]);
    if (i < AA * HH) {
        int a = i >> 8, h = i & 255;
        g_Wt_dech[i] = __float2half(Wad[h * AA + a]);
    }
    if (i < NG) {
        int j = i >> 2, g = i & 3;
        int n = g * 256 + j;
        g_wcol0r[i] = Wih0[n * 257];
        g_bias0r[i] = bih0[n] + bhh0[n];
        g_bias1r[i] = bih1[n] + bhh1[n];
    }
}

__global__ void prep_eo(const float* __restrict__ eo) {
    int i = blockIdx.x * blockDim.x + threadIdx.x;
    const float4 v = ((const float4*)eo)[i];
    __half2 h[2] = {__floats2half2_rn(v.x, v.y), __floats2half2_rn(v.z, v.w)};
    ((uint2*)g_eo_h)[i] = *(uint2*)h;
}

// ---------------- enc_proj: single fp16 MMA, 128x64 tile, double-buffered (R12) ----------------
__global__ __launch_bounds__(256) void encproj_mma() {
    __shared__ __half sA[2][128 * 40], sB[2][64 * 40];
    const int m0 = blockIdx.y * 128;
    const int n0 = blockIdx.x * 64;
    const int tid = threadIdx.x, lane = tid & 31, wid = tid >> 5;
    const int wm = wid & 3, wn = wid >> 2;
    float cf[2][4][4];
#pragma unroll
    for (int mt = 0; mt < 2; mt++)
#pragma unroll
        for (int nt = 0; nt < 4; nt++)
#pragma unroll
            for (int q = 0; q < 4; q++) cf[mt][nt][q] = 0.f;
    const int aRow = tid >> 1, aCol = (tid & 1) * 8;
    const int bRow = tid >> 2, bCol = (tid & 3) * 8;
    const uint32_t aB = smem_u32(sA), bB = smem_u32(sB);
    const int arow = wm * 32 + (lane & 15);
    const int acol8 = 8 * (lane >> 4);
    const int brow8 = (lane & 7);
    const int bcol8 = 8 * ((lane >> 3) & 1);

    uint4 ra0 = *(const uint4*)&g_eo_h[(size_t)(m0 + aRow) * 256 + aCol];
    uint4 ra1 = *(const uint4*)&g_eo_h[(size_t)(m0 + aRow) * 256 + aCol + 16];
    uint4 rb = *(const uint4*)&g_Wt_ench[(size_t)(n0 + bRow) * 256 + bCol];
#pragma unroll
    for (int it = 0; it < 8; it++) {
        const int buf = it & 1;
        *(uint4*)&sA[buf][aRow * 40 + aCol] = ra0;
        *(uint4*)&sA[buf][aRow * 40 + aCol + 16] = ra1;
        *(uint4*)&sB[buf][bRow * 40 + bCol] = rb;
        __syncthreads();
        if (it < 7) {
            const int kc = (it + 1) * 32;
            ra0 = *(const uint4*)&g_eo_h[(size_t)(m0 + aRow) * 256 + kc + aCol];
            ra1 = *(const uint4*)&g_eo_h[(size_t)(m0 + aRow) * 256 + kc + aCol + 16];
            rb = *(const uint4*)&g_Wt_ench[(size_t)(n0 + bRow) * 256 + kc + bCol];
        }
        const uint32_t offA = buf * (128 * 40) * 2;
        const uint32_t offB = buf * (64 * 40) * 2;
#pragma unroll
        for (int ks = 0; ks < 32; ks += 16) {
            uint32_t a[2][4], b[4][2];
#pragma unroll
            for (int mt = 0; mt < 2; mt++)
                ldsm_x4(aB + offA + ((arow + mt * 16) * 40 + ks + acol8) * 2,
                        a[mt][0], a[mt][1], a[mt][2], a[mt][3]);
#pragma unroll
            for (int nt = 0; nt < 4; nt++)
                ldsm_x2(bB + offB + ((wn * 32 + nt * 8 + brow8) * 40 + ks + bcol8) * 2,
                        b[nt][0], b[nt][1]);
#pragma unroll
            for (int mt = 0; mt < 2; mt++)
#pragma unroll
                for (int nt = 0; nt < 4; nt++)
                    mma16816(cf[mt][nt], a[mt][0], a[mt][1], a[mt][2], a[mt][3],
                             b[nt][0], b[nt][1]);
        }
    }
    const int erow = wm * 32 + (lane >> 2);
    const int ecol0 = wn * 32 + (lane & 3) * 2;
#pragma unroll
    for (int mt = 0; mt < 2; mt++)
#pragma unroll
        for (int nt = 0; nt < 4; nt++) {
            int r = m0 + erow + mt * 16, c = n0 + ecol0 + nt * 8;
            *(__half2*)&g_ep_h[(size_t)r * AA + c] = __floats2half2_rn(cf[mt][nt][0], cf[mt][nt][1]);
            *(__half2*)&g_ep_h[(size_t)(r + 8) * AA + c] = __floats2half2_rn(cf[mt][nt][2], cf[mt][nt][3]);
        }
}

// ---------------- fused attention (per step) + prev-step fc2 finalize ----------------
__global__ __launch_bounds__(256) void attn_step(const float* __restrict__ v,
                                                 float* __restrict__ attn_out,
                                                 const float* __restrict__ bfc2,
                                                 float* __restrict__ outs, int s) {
    __shared__ float s_dp[256];
    __shared__ float s_v[256];
    __shared__ float s_sc[512];
    __shared__ float s_red[8];
    __shared__ float s_ctx[8][256];
    const int b = blockIdx.x;
    const int tid = threadIdx.x;
    const int lane = tid & 31, w = tid >> 5;

    if (s > 0 && tid == 0) {
        const float4 p = *(const float4*)&g_fcp4[b * 4];
        float o = (p.x + p.y) + (p.z + p.w) + bfc2[0];
        outs[b * TPRED + (s - 1)] = o;
        g_dec_in[b] = o;
    }

    s_dp[tid] = g_dp[b * 256 + tid];
    s_v[tid] = v[tid];
    __syncthreads();

    float vr[8], dr[8];
#pragma unroll
    for (int i = 0; i < 8; i++) {
        vr[i] = s_v[lane * 8 + i];
        dr[i] = s_dp[lane * 8 + i];
    }

    const __half* ep = g_ep_h + (size_t)b * THIST * AA;
    for (int i0 = 0; i0 < 64; i0 += 8) {
        int4 raw[8];
#pragma unroll
        for (int u = 0; u < 8; u++) {
            int t = w + (i0 + u) * 8;
            raw[u] = ldcs_int4(ep + (size_t)t * AA + lane * 8);
        }
        float ss[8];
#pragma unroll
        for (int u = 0; u < 8; u++) {
            const __half2* hp = (const __half2*)&raw[u];
            float acc = 0.f;
#pragma unroll
            for (int q = 0; q < 4; q++) {
                float2 f = __half22float2(hp[q]);
                acc = fmaf(vr[2 * q + 0], ftanh_fast(f.x + dr[2 * q + 0]), acc);
                acc = fmaf(vr[2 * q + 1], ftanh_fast(f.y + dr[2 * q + 1]), acc);
            }
            ss[u] = acc;
        }
#pragma unroll
        for (int off = 16; off; off >>= 1)
#pragma unroll
            for (int u = 0; u < 8; u++) ss[u] += __shfl_xor_sync(0xffffffffu, ss[u], off);
        if (lane == 0) {
#pragma unroll
            for (int u = 0; u < 8; u++) s_sc[w + (i0 + u) * 8] = ss[u];
        }
    }
    __syncthreads();

    float m = fmaxf(s_sc[tid], s_sc[tid + 256]);
#pragma unroll
    for (int off = 16; off; off >>= 1) m = fmaxf(m, __shfl_xor_sync(0xffffffffu, m, off));
    if (lane == 0) s_red[w] = m;
    __syncthreads();
    float mm = s_red[0];
#pragma unroll
    for (int i = 1; i < 8; i++) mm = fmaxf(mm, s_red[i]);
    float e0 = __expf(s_sc[tid] - mm);
    float e1 = __expf(s_sc[tid + 256] - mm);
    float sm = e0 + e1;
#pragma unroll
    for (int off = 16; off; off >>= 1) sm += __shfl_xor_sync(0xffffffffu, sm, off);
    __syncthreads();
    if (lane == 0) s_red[w] = sm;
    __syncthreads();
    float tot = s_red[0];
#pragma unroll
    for (int i = 1; i < 8; i++) tot += s_red[i];
    float inv = 1.f / tot;
    float p0 = e0 * inv, p1 = e1 * inv;
    s_sc[tid] = p0;
    s_sc[tid + 256] = p1;
    attn_out[(size_t)b * THIST + tid] = p0;
    attn_out[(size_t)b * THIST + tid + 256] = p1;
    __syncthreads();

    const __half* eob = g_eo_h + (size_t)b * THIST * HENC;
    float cacc[8];
#pragma unroll
    for (int q = 0; q < 8; q++) cacc[q] = 0.f;
    for (int i0 = 0; i0 < 64; i0 += 8) {
        int4 r[8];
        float p[8];
#pragma unroll
        for (int u = 0; u < 8; u++) {
            int t = w + (i0 + u) * 8;
            r[u] = ldcs_int4(eob + (size_t)t * HENC + lane * 8);
            p[u] = s_sc[t];
        }
#pragma unroll
        for (int u = 0; u < 8; u++) {
            const __half2* hp = (const __half2*)&r[u];
#pragma unroll
            for (int q = 0; q < 4; q++) {
                float2 f = __half22float2(hp[q]);
                cacc[2 * q + 0] = fmaf(p[u], f.x, cacc[2 * q + 0]);
                cacc[2 * q + 1] = fmaf(p[u], f.y, cacc[2 * q + 1]);
            }
        }
    }
#pragma unroll
    for (int q = 0; q < 8; q++) s_ctx[w][lane * 8 + q] = cacc[q];
    __syncthreads();

    const int e = tid;
    float csum = 0.f;
#pragma unroll
    for (int q = 0; q < 8; q++) csum += s_ctx[q][e];
    g_xcat0h[b * 512 + e] = __float2half(csum);
    g_xcat0h[b * 512 + 256 + e] = __float2half(g_h0[b * 256 + e]);
    g_xcatfch[b * 512 + 256 + e] = __float2half(csum);
}

// ---------------- double-buffered fp16 MMA 64x64 tile GEMM core, K-slab 64 ----------------
__device__ void gemm_mma_db(const __half* __restrict__ A, int lda,
                            const __half* __restrict__ B, int ldb,
                            int m0, int n0, int ktot, float cf[2][2][4]) {
    static __shared__ __half sA[2][64 * 72];
    static __shared__ __half sB[2][64 * 72];
    const int tid = threadIdx.x, lane = tid & 31, wid = tid >> 5;
    const int wm = wid & 1, wn = wid >> 1;
#pragma unroll
    for (int mt = 0; mt < 2; mt++)
#pragma unroll
        for (int nt = 0; nt < 2; nt++)
#pragma unroll
            for (int q = 0; q < 4; q++) cf[mt][nt][q] = 0.f;
    const int lrow = tid >> 2, lcol = (tid & 3) * 16;   // 2 uint4 per row-slab per matrix
    const uint32_t aBase = smem_u32(sA), bBase = smem_u32(sB);
    const int arow = wm * 32 + (lane & 15);
    const int acol8 = 8 * (lane >> 4);
    const int brow = wn * 16 + (lane & 7);
    const int bcol8 = 8 * ((lane >> 3) & 1);
    const int niter = ktot / 64;

    uint4 ra0 = *(const uint4*)&A[(size_t)(m0 + lrow) * lda + lcol];
    uint4 ra1 = *(const uint4*)&A[(size_t)(m0 + lrow) * lda + lcol + 8];
    uint4 rb0 = *(const uint4*)&B[(size_t)(n0 + lrow) * ldb + lcol];
    uint4 rb1 = *(const uint4*)&B[(size_t)(n0 + lrow) * ldb + lcol + 8];
    for (int it = 0; it < niter; it++) {
        const int buf = it & 1;
        *(uint4*)&sA[buf][lrow * 72 + lcol] = ra0;
        *(uint4*)&sA[buf][lrow * 72 + lcol + 8] = ra1;
        *(uint4*)&sB[buf][lrow * 72 + lcol] = rb0;
        *(uint4*)&sB[buf][lrow * 72 + lcol + 8] = rb1;
        __syncthreads();
        if (it + 1 < niter) {
            const int kc = (it + 1) * 64;
            ra0 = *(const uint4*)&A[(size_t)(m0 + lrow) * lda + kc + lcol];
            ra1 = *(const uint4*)&A[(size_t)(m0 + lrow) * lda + kc + lcol + 8];
            rb0 = *(const uint4*)&B[(size_t)(n0 + lrow) * ldb + kc + lcol];
            rb1 = *(const uint4*)&B[(size_t)(n0 + lrow) * ldb + kc + lcol + 8];
        }
        const uint32_t off = buf * (64 * 72) * 2;
#pragma unroll
        for (int ks = 0; ks < 64; ks += 16) {
            uint32_t a[2][4], bfrag[2][2];
#pragma unroll
            for (int mt = 0; mt < 2; mt++)
                ldsm_x4(aBase + off + ((arow + mt * 16) * 72 + ks + acol8) * 2,
                        a[mt][0], a[mt][1], a[mt][2], a[mt][3]);
#pragma unroll
            for (int nt = 0; nt < 2; nt++)
                ldsm_x2(bBase + off + ((brow + nt * 8) * 72 + ks + bcol8) * 2,
                        bfrag[nt][0], bfrag[nt][1]);
#pragma unroll
            for (int mt = 0; mt < 2; mt++)
#pragma unroll
                for (int nt = 0; nt < 2; nt++)
                    mma16816(cf[mt][nt], a[mt][0], a[mt][1], a[mt][2], a[mt][3],
                             bfrag[nt][0], bfrag[nt][1]);
        }
    }
}

// ---------------- fused recurrent step: 3 phases, 2 barriers ----------------
__global__ __launch_bounds__(256) void recurrent_step(const float* __restrict__ bfc1,
                                                      const float* __restrict__ Wfc2) {
    unsigned eps = 0;
    if (threadIdx.x == 0) eps = atomicAdd(&g_sense, 0);
    const int cta = blockIdx.x;
    const int tid = threadIdx.x;
    const int lane = tid & 31, wid = tid >> 5;
    const int wm = wid & 1, wn = wid >> 1;
    const int parity = lane & 1;
    float cf[2][2][4];

    // ===== P0: lstm0 gates GEMM + cell0 epilogue =====
    {
        const int m0 = (cta & 7) * 64, n0 = (cta >> 3) * 64;
        gemm_mma_db(g_xcat0h, 512, g_Wcat0rh, 512, m0, n0, 512, cf);
#pragma unroll
        for (int mt = 0; mt < 2; mt++)
#pragma unroll
            for (int nt = 0; nt < 2; nt++) {
                float t0 = __shfl_xor_sync(0xffffffffu, cf[mt][nt][0], 1);
                float t1 = __shfl_xor_sync(0xffffffffu, cf[mt][nt][1], 1);
                float t2 = __shfl_xor_sync(0xffffffffu, cf[mt][nt][2], 1);
                float t3 = __shfl_xor_sync(0xffffffffu, cf[mt][nt][3], 1);
                const int c = n0 + wn * 16 + (lane & 3) * 2 + nt * 8;
                const int j = c >> 2;
                const int r = m0 + wm * 32 + (lane >> 2) + mt * 16;
                int b;
                float gi, gf, gg, go;
                if (!parity) { b = r;     gi = cf[mt][nt][0]; gf = cf[mt][nt][1]; gg = t0; go = t1; }
                else         { b = r + 8; gi = t2;            gf = t3;            gg = cf[mt][nt][2]; go = cf[mt][nt][3]; }
                const float din = g_dec_in[b];
                const float4 wc = *(const float4*)&g_wcol0r[4 * j];
                const float4 bs = *(const float4*)&g_bias0r[4 * j];
                gi += din * wc.x + bs.x;
                gf += din * wc.y + bs.y;
                gg += din * wc.z + bs.z;
                go += din * wc.w + bs.w;
                const int idx = b * 256 + j;
                float cc = sig_precise(gf) * g_c0[idx] + sig_precise(gi) * tanhf(gg);
                float hh = sig_precise(go) * tanhf(cc);
                g_c0[idx] = cc;
                g_h0[idx] = hh;
                g_xcat1h[b * 512 + j] = __float2half(hh);
                g_xcat1h[b * 512 + 256 + j] = __float2half(g_h1[idx]);
            }
    }
    grid_barrier(&eps);

    // ===== P1: lstm1 gates GEMM + cell1 epilogue =====
    {
        const int m0 = (cta & 7) * 64, n0 = (cta >> 3) * 64;
        gemm_mma_db(g_xcat1h, 512, g_Wcat1rh, 512, m0, n0, 512, cf);
#pragma unroll
        for (int mt = 0; mt < 2; mt++)
#pragma unroll
            for (int nt = 0; nt < 2; nt++) {
                float t0 = __shfl_xor_sync(0xffffffffu, cf[mt][nt][0], 1);
                float t1 = __shfl_xor_sync(0xffffffffu, cf[mt][nt][1], 1);
                float t2 = __shfl_xor_sync(0xffffffffu, cf[mt][nt][2], 1);
                float t3 = __shfl_xor_sync(0xffffffffu, cf[mt][nt][3], 1);
                const int c = n0 + wn * 16 + (lane & 3) * 2 + nt * 8;
                const int j = c >> 2;
                const int r = m0 + wm * 32 + (lane >> 2) + mt * 16;
                int b;
                float gi, gf, gg, go;
                if (!parity) { b = r;     gi = cf[mt][nt][0]; gf = cf[mt][nt][1]; gg = t0; go = t1; }
                else         { b = r + 8; gi = t2;            gf = t3;            gg = cf[mt][nt][2]; go = cf[mt][nt][3]; }
                const float4 bs = *(const float4*)&g_bias1r[4 * j];
                gi += bs.x;
                gf += bs.y;
                gg += bs.z;
                go += bs.w;
                const int idx = b * 256 + j;
                float cc = sig_precise(gf) * g_c1[idx] + sig_precise(gi) * tanhf(gg);
                float hh = sig_precise(go) * tanhf(cc);
                g_c1[idx] = cc;
                g_h1[idx] = hh;
                g_xcatfch[b * 512 + j] = __float2half(hh);
            }
    }
    grid_barrier(&eps);

    // ===== P2: fc1+relu+Wfc2 partial (ctas 0-31) | dec_proj (ctas 32-63) =====
    if (cta < 32) {
        __shared__ float sfc[64][4];
        const int m0 = (cta & 7) * 64, n0 = (cta >> 3) * 64;
        gemm_mma_db(g_xcatfch, 512, g_Wfc1h, 512, m0, n0, 512, cf);
        float s0[2] = {0.f, 0.f}, s1[2] = {0.f, 0.f};
#pragma unroll
        for (int mt = 0; mt < 2; mt++)
#pragma unroll
            for (int nt = 0; nt < 2; nt++) {
                const int c = n0 + wn * 16 + (lane & 3) * 2 + nt * 8;
                const float b0 = bfc1[c], b1 = bfc1[c + 1];
                const float w0 = Wfc2[c], w1 = Wfc2[c + 1];
                s0[mt] += fmaxf(cf[mt][nt][0] + b0, 0.f) * w0 + fmaxf(cf[mt][nt][1] + b1, 0.f) * w1;
                s1[mt] += fmaxf(cf[mt][nt][2] + b0, 0.f) * w0 + fmaxf(cf[mt][nt][3] + b1, 0.f) * w1;
            }
#pragma unroll
        for (int off = 1; off < 4; off <<= 1) {
#pragma unroll
            for (int mt = 0; mt < 2; mt++) {
                s0[mt] += __shfl_xor_sync(0xffffffffu, s0[mt], off);
                s1[mt] += __shfl_xor_sync(0xffffffffu, s1[mt], off);
            }
        }
        if ((lane & 3) == 0) {
#pragma unroll
            for (int mt = 0; mt < 2; mt++) {
                int rl = wm * 32 + (lane >> 2) + mt * 16;
                sfc[rl][wn] = s0[mt];
                sfc[rl + 8][wn] = s1[mt];
            }
        }
        __syncthreads();
        if (tid < 64) {
            float p = sfc[tid][0] + sfc[tid][1] + sfc[tid][2] + sfc[tid][3];
            g_fcp4[(m0 + tid) * 4 + (cta >> 3)] = p;
        }
    } else if (cta < 64) {
        const int c2 = cta - 32;
        const int m0 = (c2 & 7) * 64, n0 = (c2 >> 3) * 64;
        gemm_mma_db(g_xcatfch, 512, g_Wt_dech, 256, m0, n0, 256, cf);
        const int erow = wm * 32 + (lane >> 2);
        const int ecol = wn * 16 + (lane & 3) * 2;
#pragma unroll
        for (int mt = 0; mt < 2; mt++)
#pragma unroll
            for (int nt = 0; nt < 2; nt++) {
                int r = m0 + erow + mt * 16, c = n0 + ecol + nt * 8;
                *(float2*)&g_dp[(size_t)r * AA + c] = make_float2(cf[mt][nt][0], cf[mt][nt][1]);
                *(float2*)&g_dp[(size_t)(r + 8) * AA + c] = make_float2(cf[mt][nt][2], cf[mt][nt][3]);
            }
    }
}

// ---------------- finalize last step's fc output ----------------
__global__ void finalize(const float* __restrict__ bfc2, float* __restrict__ outs) {
    int b = blockIdx.x * 256 + threadIdx.x;
    const float4 p = *(const float4*)&g_fcp4[b * 4];
    outs[b * TPRED + (TPRED - 1)] = (p.x + p.y) + (p.z + p.w) + bfc2[0];
}

// ---------------- initial dec_proj from encoder_hidden[1] ----------------
__global__ __launch_bounds__(256) void dp_init(const float* __restrict__ Wad) {
    __shared__ float sA[8][256];
    const int b0 = blockIdx.x * 8;
    const int tid = threadIdx.x;
#pragma unroll
    for (int q = 0; q < 2; q++) {
        int f4 = q * 256 + tid;
        int r = f4 >> 6, c = (f4 & 63) * 4;
        *(float4*)&sA[r][c] = *(const float4*)&g_h1[(size_t)(b0 + r) * 256 + c];
    }
    __syncthreads();
    float dpa[8];
#pragma unroll
    for (int r = 0; r < 8; r++) dpa[r] = 0.f;
#pragma unroll 4
    for (int h = 0; h < 256; h++) {
        const float wv = Wad[(size_t)h * AA + tid];
#pragma unroll
        for (int r = 0; r < 8; r++) dpa[r] = fmaf(sA[r][h], wv, dpa[r]);
    }
#pragma unroll
    for (int r = 0; r < 8; r++) g_dp[(b0 + r) * 256 + tid] = dpa[r];
}

// ---------------- host launcher ----------------
extern "C" void kernel_launch(void* const* d_in, const int* in_sizes, int n_in,
                              void* d_out, int out_size) {
    int off = (in_sizes[0] == 1) ? 1 : 0;
    const float* enc_out = (const float*)d_in[off + 0];
    const float* enc_h = (const float*)d_in[off + 1];
    const float* enc_c = (const float*)d_in[off + 2];
    const float* Wae = (const float*)d_in[off + 3];
    const float* Wad = (const float*)d_in[off + 4];
    const float* v = (const float*)d_in[off + 5];
    const float* Wih0 = (const float*)d_in[off + 6];
    const float* Whh0 = (const float*)d_in[off + 7];
    const float* bih0 = (const float*)d_in[off + 8];
    const float* bhh0 = (const float*)d_in[off + 9];
    const float* Wih1 = (const float*)d_in[off + 10];
    const float* Whh1 = (const float*)d_in[off + 11];
    const float* bih1 = (const float*)d_in[off + 12];
    const float* bhh1 = (const float*)d_in[off + 13];
    const float* Wfc1 = (const float*)d_in[off + 14];
    const float* bfc1 = (const float*)d_in[off + 15];
    const float* Wfc2 = (const float*)d_in[off + 16];
    const float* bfc2 = (const float*)d_in[off + 17];

    float* out = (float*)d_out;
    float* attn_base = out + (size_t)BB * TPRED;

    init_state<<<(BB * HH + 255) / 256, 256>>>(enc_h, enc_c);
    prep<<<2048, 256>>>(Wae, Wad, Wih0, Whh0, bih0, bhh0, Wih1, Whh1, bih1, bhh1, Wfc1);
    prep_eo<<<(BB * THIST * HENC / 4) / 256, 256>>>(enc_out);
    encproj_mma<<<dim3(4, 2048), 256>>>();
    dp_init<<<BB / 8, 256>>>(Wad);

    for (int s = 0; s < TPRED; s++) {
        attn_step<<<BB, 256>>>(v, attn_base + (size_t)s * BB * THIST, bfc2, out, s);
        recurrent_step<<<NCTAS, 256>>>(bfc1, Wfc2);
    }
    finalize<<<2, 256>>>(bfc2, out);
    (void)n_in;
    (void)out_size;
}

// round 15
// speedup vs baseline: 1.0803x; 1.0178x over previous
#include <cuda_runtime.h>
#include <cuda_fp16.h>
#include <cstdint>

#define BB 512
#define THIST 512
#define HENC 256
#define HH 256
#define AA 256
#define TPRED 32
#define NG 1024
#define NCTAS 128

// ---------------- device scratch (static only) ----------------
__device__ __half g_ep_h[(size_t)BB * THIST * AA];
__device__ __half g_eo_h[(size_t)BB * THIST * HENC];
__device__ __half g_Wt_ench[HENC * AA];
__device__ __half g_Wcat0rh[NG * 512];
__device__ __half g_Wcat1rh[NG * 512];
__device__ __half g_Wfc1h[HH * 512];
__device__ __half g_Wt_dech[AA * HH];
__device__ float g_wcol0r[NG];
__device__ float g_bias0r[NG];
__device__ float g_bias1r[NG];
__device__ float g_h0[BB * HH], g_h1[BB * HH];
__device__ float g_c0[BB * HH], g_c1[BB * HH];
__device__ float g_dec_in[BB];
__device__ float g_dp[BB * AA];
__device__ float g_fcp4[BB * 4];
__device__ __half g_xcat0h[BB * 512];
__device__ __half g_xcat1h[BB * 512];
__device__ __half g_xcatfch[BB * 512];

__device__ unsigned g_count = 0;
__device__ unsigned g_sense = 0;

// ---------------- helpers ----------------
__device__ __forceinline__ float ftanh_fast(float x) {
    float y;
    asm("tanh.approx.f32 %0, %1;" : "=f"(y) : "f"(x));
    return y;
}
__device__ __forceinline__ float sig_precise(float x) { return 1.f / (1.f + expf(-x)); }

__device__ __forceinline__ uint32_t smem_u32(const void* p) {
    uint32_t a;
    asm("{.reg .u64 t; cvta.to.shared.u64 t, %1; cvt.u32.u64 %0, t;}" : "=r"(a) : "l"(p));
    return a;
}
__device__ __forceinline__ void ldsm_x4(uint32_t addr, uint32_t& r0, uint32_t& r1,
                                        uint32_t& r2, uint32_t& r3) {
    asm volatile("ldmatrix.sync.aligned.m8n8.x4.shared.b16 {%0,%1,%2,%3}, [%4];"
                 : "=r"(r0), "=r"(r1), "=r"(r2), "=r"(r3) : "r"(addr));
}
__device__ __forceinline__ void ldsm_x2(uint32_t addr, uint32_t& r0, uint32_t& r1) {
    asm volatile("ldmatrix.sync.aligned.m8n8.x2.shared.b16 {%0,%1}, [%2];"
                 : "=r"(r0), "=r"(r1) : "r"(addr));
}
__device__ __forceinline__ void mma16816(float* d, uint32_t a0, uint32_t a1, uint32_t a2,
                                         uint32_t a3, uint32_t b0, uint32_t b1) {
    asm volatile(
        "mma.sync.aligned.m16n8k16.row.col.f32.f16.f16.f32 "
        "{%0,%1,%2,%3},{%4,%5,%6,%7},{%8,%9},{%0,%1,%2,%3};"
        : "+f"(d[0]), "+f"(d[1]), "+f"(d[2]), "+f"(d[3])
        : "r"(a0), "r"(a1), "r"(a2), "r"(a3), "r"(b0), "r"(b1));
}
__device__ __forceinline__ int4 ldcs_int4(const void* p) {
    int4 v;
    asm volatile("ld.global.cs.v4.b32 {%0,%1,%2,%3}, [%4];"
                 : "=r"(v.x), "=r"(v.y), "=r"(v.z), "=r"(v.w) : "l"(p));
    return v;
}

__device__ __forceinline__ void grid_barrier(unsigned* eps) {
    __syncthreads();
    if (threadIdx.x == 0) {
        unsigned target = ++(*eps);
        __threadfence();
        unsigned old = atomicAdd(&g_count, 1);
        if (old == NCTAS - 1) {
            g_count = 0;
            __threadfence();
            atomicExch(&g_sense, target);
        } else {
            while (atomicAdd(&g_sense, 0) != target) __nanosleep(64);
        }
    }
    __syncthreads();
}

// ---------------- init + prep ----------------
__global__ void init_state(const float* __restrict__ eh, const float* __restrict__ ec) {
    int i = blockIdx.x * blockDim.x + threadIdx.x;
    if (i < BB * HH) {
        g_h0[i] = eh[i];
        g_h1[i] = eh[BB * HH + i];
        g_c0[i] = ec[i];
        g_c1[i] = ec[BB * HH + i];
    }
    if (i < BB) g_dec_in[i] = 0.f;
}

__global__ void prep(const float* __restrict__ Wae, const float* __restrict__ Wad,
                     const float* __restrict__ Wih0, const float* __restrict__ Whh0,
                     const float* __restrict__ bih0, const float* __restrict__ bhh0,
                     const float* __restrict__ Wih1, const float* __restrict__ Whh1,
                     const float* __restrict__ bih1, const float* __restrict__ bhh1,
                     const float* __restrict__ Wfc1) {
    int i = blockIdx.x * blockDim.x + threadIdx.x;
    if (i < HENC * AA) {
        int a = i / HENC, e = i % HENC;
        g_Wt_ench[i] = __float2half(Wae[e * AA + a]);
    }
    if (i < NG * 512) {
        int n4 = i >> 9, c = i & 511;
        int j = n4 >> 2, g = n4 & 3;
        int n = g * 256 + j;
        g_Wcat0rh[i] = __float2half((c < 256) ? Wih0[n * 257 + 1 + c] : Whh0[n * 256 + (c - 256)]);
        g_Wcat1rh[i] = __float2half((c < 256) ? Wih1[n * 256 + c] : Whh1[n * 256 + (c - 256)]);
    }
    if (i < HH * 512) g_Wfc1h[i] = __float2half(Wfc1[i]);
    if (i < AA * HH) {
        int a = i >> 8, h = i & 255;
        g_Wt_dech[i] = __float2half(Wad[h * AA + a]);
    }
    if (i < NG) {
        int j = i >> 2, g = i & 3;
        int n = g * 256 + j;
        g_wcol0r[i] = Wih0[n * 257];
        g_bias0r[i] = bih0[n] + bhh0[n];
        g_bias1r[i] = bih1[n] + bhh1[n];
    }
}

__global__ void prep_eo(const float* __restrict__ eo) {
    int i = blockIdx.x * blockDim.x + threadIdx.x;
    const float4 v = ((const float4*)eo)[i];
    __half2 h[2] = {__floats2half2_rn(v.x, v.y), __floats2half2_rn(v.z, v.w)};
    ((uint2*)g_eo_h)[i] = *(uint2*)h;
}

// ---------------- enc_proj: single fp16 MMA, 128x64 tile, K-slab 64, double-buffered ----------------
__global__ __launch_bounds__(256) void encproj_mma() {
    __shared__ __half sA[2][128 * 72], sB[2][64 * 72];
    const int m0 = blockIdx.y * 128;
    const int n0 = blockIdx.x * 64;
    const int tid = threadIdx.x, lane = tid & 31, wid = tid >> 5;
    const int wm = wid & 3, wn = wid >> 2;
    float cf[2][4][4];
#pragma unroll
    for (int mt = 0; mt < 2; mt++)
#pragma unroll
        for (int nt = 0; nt < 4; nt++)
#pragma unroll
            for (int q = 0; q < 4; q++) cf[mt][nt][q] = 0.f;
    // loaders: A 128 rows x 64 cols (4 uint4/thread), B 64 rows x 64 cols (2 uint4/thread)
    const int aRow = tid >> 1, aCol = (tid & 1) * 32;
    const int bRow = tid >> 2, bCol = (tid & 3) * 16;
    const uint32_t aB = smem_u32(sA), bB = smem_u32(sB);
    const int arow = wm * 32 + (lane & 15);
    const int acol8 = 8 * (lane >> 4);
    const int brow8 = (lane & 7);
    const int bcol8 = 8 * ((lane >> 3) & 1);

    uint4 ra[4], rb[2];
#pragma unroll
    for (int q = 0; q < 4; q++)
        ra[q] = *(const uint4*)&g_eo_h[(size_t)(m0 + aRow) * 256 + aCol + q * 8];
#pragma unroll
    for (int q = 0; q < 2; q++)
        rb[q] = *(const uint4*)&g_Wt_ench[(size_t)(n0 + bRow) * 256 + bCol + q * 8];
#pragma unroll
    for (int it = 0; it < 4; it++) {
        const int buf = it & 1;
#pragma unroll
        for (int q = 0; q < 4; q++) *(uint4*)&sA[buf][aRow * 72 + aCol + q * 8] = ra[q];
#pragma unroll
        for (int q = 0; q < 2; q++) *(uint4*)&sB[buf][bRow * 72 + bCol + q * 8] = rb[q];
        __syncthreads();
        if (it < 3) {
            const int kc = (it + 1) * 64;
#pragma unroll
            for (int q = 0; q < 4; q++)
                ra[q] = *(const uint4*)&g_eo_h[(size_t)(m0 + aRow) * 256 + kc + aCol + q * 8];
#pragma unroll
            for (int q = 0; q < 2; q++)
                rb[q] = *(const uint4*)&g_Wt_ench[(size_t)(n0 + bRow) * 256 + kc + bCol + q * 8];
        }
        const uint32_t offA = buf * (128 * 72) * 2;
        const uint32_t offB = buf * (64 * 72) * 2;
#pragma unroll
        for (int ks = 0; ks < 64; ks += 16) {
            uint32_t a[2][4], b[4][2];
#pragma unroll
            for (int mt = 0; mt < 2; mt++)
                ldsm_x4(aB + offA + ((arow + mt * 16) * 72 + ks + acol8) * 2,
                        a[mt][0], a[mt][1], a[mt][2], a[mt][3]);
#pragma unroll
            for (int nt = 0; nt < 4; nt++)
                ldsm_x2(bB + offB + ((wn * 32 + nt * 8 + brow8) * 72 + ks + bcol8) * 2,
                        b[nt][0], b[nt][1]);
#pragma unroll
            for (int mt = 0; mt < 2; mt++)
#pragma unroll
                for (int nt = 0; nt < 4; nt++)
                    mma16816(cf[mt][nt], a[mt][0], a[mt][1], a[mt][2], a[mt][3],
                             b[nt][0], b[nt][1]);
        }
    }
    const int erow = wm * 32 + (lane >> 2);
    const int ecol0 = wn * 32 + (lane & 3) * 2;
#pragma unroll
    for (int mt = 0; mt < 2; mt++)
#pragma unroll
        for (int nt = 0; nt < 4; nt++) {
            int r = m0 + erow + mt * 16, c = n0 + ecol0 + nt * 8;
            *(__half2*)&g_ep_h[(size_t)r * AA + c] = __floats2half2_rn(cf[mt][nt][0], cf[mt][nt][1]);
            *(__half2*)&g_ep_h[(size_t)(r + 8) * AA + c] = __floats2half2_rn(cf[mt][nt][2], cf[mt][nt][3]);
        }
}

// ---------------- fused attention (per step) + prev-step fc2 finalize ----------------
__global__ __launch_bounds__(256) void attn_step(const float* __restrict__ v,
                                                 float* __restrict__ attn_out,
                                                 const float* __restrict__ bfc2,
                                                 float* __restrict__ outs, int s) {
    __shared__ float s_dp[256];
    __shared__ float s_v[256];
    __shared__ float s_sc[512];
    __shared__ float s_red[8];
    __shared__ float s_ctx[8][256];
    const int b = blockIdx.x;
    const int tid = threadIdx.x;
    const int lane = tid & 31, w = tid >> 5;

    if (s > 0 && tid == 0) {
        const float4 p = *(const float4*)&g_fcp4[b * 4];
        float o = (p.x + p.y) + (p.z + p.w) + bfc2[0];
        outs[b * TPRED + (s - 1)] = o;
        g_dec_in[b] = o;
    }

    s_dp[tid] = g_dp[b * 256 + tid];
    s_v[tid] = v[tid];
    __syncthreads();

    float vr[8], dr[8];
#pragma unroll
    for (int i = 0; i < 8; i++) {
        vr[i] = s_v[lane * 8 + i];
        dr[i] = s_dp[lane * 8 + i];
    }

    const __half* ep = g_ep_h + (size_t)b * THIST * AA;
    for (int i0 = 0; i0 < 64; i0 += 8) {
        int4 raw[8];
#pragma unroll
        for (int u = 0; u < 8; u++) {
            int t = w + (i0 + u) * 8;
            raw[u] = ldcs_int4(ep + (size_t)t * AA + lane * 8);
        }
        float ss[8];
#pragma unroll
        for (int u = 0; u < 8; u++) {
            const __half2* hp = (const __half2*)&raw[u];
            float acc = 0.f;
#pragma unroll
            for (int q = 0; q < 4; q++) {
                float2 f = __half22float2(hp[q]);
                acc = fmaf(vr[2 * q + 0], ftanh_fast(f.x + dr[2 * q + 0]), acc);
                acc = fmaf(vr[2 * q + 1], ftanh_fast(f.y + dr[2 * q + 1]), acc);
            }
            ss[u] = acc;
        }
#pragma unroll
        for (int off = 16; off; off >>= 1)
#pragma unroll
            for (int u = 0; u < 8; u++) ss[u] += __shfl_xor_sync(0xffffffffu, ss[u], off);
        if (lane == 0) {
#pragma unroll
            for (int u = 0; u < 8; u++) s_sc[w + (i0 + u) * 8] = ss[u];
        }
    }
    __syncthreads();

    float m = fmaxf(s_sc[tid], s_sc[tid + 256]);
#pragma unroll
    for (int off = 16; off; off >>= 1) m = fmaxf(m, __shfl_xor_sync(0xffffffffu, m, off));
    if (lane == 0) s_red[w] = m;
    __syncthreads();
    float mm = s_red[0];
#pragma unroll
    for (int i = 1; i < 8; i++) mm = fmaxf(mm, s_red[i]);
    float e0 = __expf(s_sc[tid] - mm);
    float e1 = __expf(s_sc[tid + 256] - mm);
    float sm = e0 + e1;
#pragma unroll
    for (int off = 16; off; off >>= 1) sm += __shfl_xor_sync(0xffffffffu, sm, off);
    __syncthreads();
    if (lane == 0) s_red[w] = sm;
    __syncthreads();
    float tot = s_red[0];
#pragma unroll
    for (int i = 1; i < 8; i++) tot += s_red[i];
    float inv = 1.f / tot;
    float p0 = e0 * inv, p1 = e1 * inv;
    s_sc[tid] = p0;
    s_sc[tid + 256] = p1;
    attn_out[(size_t)b * THIST + tid] = p0;
    attn_out[(size_t)b * THIST + tid + 256] = p1;
    __syncthreads();

    const __half* eob = g_eo_h + (size_t)b * THIST * HENC;
    float cacc[8];
#pragma unroll
    for (int q = 0; q < 8; q++) cacc[q] = 0.f;
    for (int i0 = 0; i0 < 64; i0 += 8) {
        int4 r[8];
        float p[8];
#pragma unroll
        for (int u = 0; u < 8; u++) {
            int t = w + (i0 + u) * 8;
            r[u] = ldcs_int4(eob + (size_t)t * HENC + lane * 8);
            p[u] = s_sc[t];
        }
#pragma unroll
        for (int u = 0; u < 8; u++) {
            const __half2* hp = (const __half2*)&r[u];
#pragma unroll
            for (int q = 0; q < 4; q++) {
                float2 f = __half22float2(hp[q]);
                cacc[2 * q + 0] = fmaf(p[u], f.x, cacc[2 * q + 0]);
                cacc[2 * q + 1] = fmaf(p[u], f.y, cacc[2 * q + 1]);
            }
        }
    }
#pragma unroll
    for (int q = 0; q < 8; q++) s_ctx[w][lane * 8 + q] = cacc[q];
    __syncthreads();

    const int e = tid;
    float csum = 0.f;
#pragma unroll
    for (int q = 0; q < 8; q++) csum += s_ctx[q][e];
    g_xcat0h[b * 512 + e] = __float2half(csum);
    g_xcat0h[b * 512 + 256 + e] = __float2half(g_h0[b * 256 + e]);
    g_xcatfch[b * 512 + 256 + e] = __float2half(csum);
}

// ---------------- double-buffered fp16 MMA 64x64 tile GEMM core, K-slab 64 ----------------
__device__ void gemm_mma_db(const __half* __restrict__ A, int lda,
                            const __half* __restrict__ B, int ldb,
                            int m0, int n0, int ktot, float cf[2][2][4]) {
    static __shared__ __half sA[2][64 * 72];
    static __shared__ __half sB[2][64 * 72];
    const int tid = threadIdx.x, lane = tid & 31, wid = tid >> 5;
    const int wm = wid & 1, wn = wid >> 1;
#pragma unroll
    for (int mt = 0; mt < 2; mt++)
#pragma unroll
        for (int nt = 0; nt < 2; nt++)
#pragma unroll
            for (int q = 0; q < 4; q++) cf[mt][nt][q] = 0.f;
    const int lrow = tid >> 2, lcol = (tid & 3) * 16;
    const uint32_t aBase = smem_u32(sA), bBase = smem_u32(sB);
    const int arow = wm * 32 + (lane & 15);
    const int acol8 = 8 * (lane >> 4);
    const int brow = wn * 16 + (lane & 7);
    const int bcol8 = 8 * ((lane >> 3) & 1);
    const int niter = ktot / 64;

    uint4 ra0 = *(const uint4*)&A[(size_t)(m0 + lrow) * lda + lcol];
    uint4 ra1 = *(const uint4*)&A[(size_t)(m0 + lrow) * lda + lcol + 8];
    uint4 rb0 = *(const uint4*)&B[(size_t)(n0 + lrow) * ldb + lcol];
    uint4 rb1 = *(const uint4*)&B[(size_t)(n0 + lrow) * ldb + lcol + 8];
    for (int it = 0; it < niter; it++) {
        const int buf = it & 1;
        *(uint4*)&sA[buf][lrow * 72 + lcol] = ra0;
        *(uint4*)&sA[buf][lrow * 72 + lcol + 8] = ra1;
        *(uint4*)&sB[buf][lrow * 72 + lcol] = rb0;
        *(uint4*)&sB[buf][lrow * 72 + lcol + 8] = rb1;
        __syncthreads();
        if (it + 1 < niter) {
            const int kc = (it + 1) * 64;
            ra0 = *(const uint4*)&A[(size_t)(m0 + lrow) * lda + kc + lcol];
            ra1 = *(const uint4*)&A[(size_t)(m0 + lrow) * lda + kc + lcol + 8];
            rb0 = *(const uint4*)&B[(size_t)(n0 + lrow) * ldb + kc + lcol];
            rb1 = *(const uint4*)&B[(size_t)(n0 + lrow) * ldb + kc + lcol + 8];
        }
        const uint32_t off = buf * (64 * 72) * 2;
#pragma unroll
        for (int ks = 0; ks < 64; ks += 16) {
            uint32_t a[2][4], bfrag[2][2];
#pragma unroll
            for (int mt = 0; mt < 2; mt++)
                ldsm_x4(aBase + off + ((arow + mt * 16) * 72 + ks + acol8) * 2,
                        a[mt][0], a[mt][1], a[mt][2], a[mt][3]);
#pragma unroll
            for (int nt = 0; nt < 2; nt++)
                ldsm_x2(bBase + off + ((brow + nt * 8) * 72 + ks + bcol8) * 2,
                        bfrag[nt][0], bfrag[nt][1]);
#pragma unroll
            for (int mt = 0; mt < 2; mt++)
#pragma unroll
                for (int nt = 0; nt < 2; nt++)
                    mma16816(cf[mt][nt], a[mt][0], a[mt][1], a[mt][2], a[mt][3],
                             bfrag[nt][0], bfrag[nt][1]);
        }
    }
}

// ---------------- fused recurrent step: 3 phases, 2 barriers ----------------
__global__ __launch_bounds__(256) void recurrent_step(const float* __restrict__ bfc1,
                                                      const float* __restrict__ Wfc2) {
    unsigned eps = 0;
    if (threadIdx.x == 0) eps = atomicAdd(&g_sense, 0);
    const int cta = blockIdx.x;
    const int tid = threadIdx.x;
    const int lane = tid & 31, wid = tid >> 5;
    const int wm = wid & 1, wn = wid >> 1;
    const int parity = lane & 1;
    float cf[2][2][4];

    // ===== P0: lstm0 gates GEMM + cell0 epilogue =====
    {
        const int m0 = (cta & 7) * 64, n0 = (cta >> 3) * 64;
        gemm_mma_db(g_xcat0h, 512, g_Wcat0rh, 512, m0, n0, 512, cf);
#pragma unroll
        for (int mt = 0; mt < 2; mt++)
#pragma unroll
            for (int nt = 0; nt < 2; nt++) {
                float t0 = __shfl_xor_sync(0xffffffffu, cf[mt][nt][0], 1);
                float t1 = __shfl_xor_sync(0xffffffffu, cf[mt][nt][1], 1);
                float t2 = __shfl_xor_sync(0xffffffffu, cf[mt][nt][2], 1);
                float t3 = __shfl_xor_sync(0xffffffffu, cf[mt][nt][3], 1);
                const int c = n0 + wn * 16 + (lane & 3) * 2 + nt * 8;
                const int j = c >> 2;
                const int r = m0 + wm * 32 + (lane >> 2) + mt * 16;
                int b;
                float gi, gf, gg, go;
                if (!parity) { b = r;     gi = cf[mt][nt][0]; gf = cf[mt][nt][1]; gg = t0; go = t1; }
                else         { b = r + 8; gi = t2;            gf = t3;            gg = cf[mt][nt][2]; go = cf[mt][nt][3]; }
                const float din = g_dec_in[b];
                const float4 wc = *(const float4*)&g_wcol0r[4 * j];
                const float4 bs = *(const float4*)&g_bias0r[4 * j];
                gi += din * wc.x + bs.x;
                gf += din * wc.y + bs.y;
                gg += din * wc.z + bs.z;
                go += din * wc.w + bs.w;
                const int idx = b * 256 + j;
                float cc = sig_precise(gf) * g_c0[idx] + sig_precise(gi) * tanhf(gg);
                float hh = sig_precise(go) * tanhf(cc);
                g_c0[idx] = cc;
                g_h0[idx] = hh;
                g_xcat1h[b * 512 + j] = __float2half(hh);
                g_xcat1h[b * 512 + 256 + j] = __float2half(g_h1[idx]);
            }
    }
    grid_barrier(&eps);

    // ===== P1: lstm1 gates GEMM + cell1 epilogue =====
    {
        const int m0 = (cta & 7) * 64, n0 = (cta >> 3) * 64;
        gemm_mma_db(g_xcat1h, 512, g_Wcat1rh, 512, m0, n0, 512, cf);
#pragma unroll
        for (int mt = 0; mt < 2; mt++)
#pragma unroll
            for (int nt = 0; nt < 2; nt++) {
                float t0 = __shfl_xor_sync(0xffffffffu, cf[mt][nt][0], 1);
                float t1 = __shfl_xor_sync(0xffffffffu, cf[mt][nt][1], 1);
                float t2 = __shfl_xor_sync(0xffffffffu, cf[mt][nt][2], 1);
                float t3 = __shfl_xor_sync(0xffffffffu, cf[mt][nt][3], 1);
                const int c = n0 + wn * 16 + (lane & 3) * 2 + nt * 8;
                const int j = c >> 2;
                const int r = m0 + wm * 32 + (lane >> 2) + mt * 16;
                int b;
                float gi, gf, gg, go;
                if (!parity) { b = r;     gi = cf[mt][nt][0]; gf = cf[mt][nt][1]; gg = t0; go = t1; }
                else         { b = r + 8; gi = t2;            gf = t3;            gg = cf[mt][nt][2]; go = cf[mt][nt][3]; }
                const float4 bs = *(const float4*)&g_bias1r[4 * j];
                gi += bs.x;
                gf += bs.y;
                gg += bs.z;
                go += bs.w;
                const int idx = b * 256 + j;
                float cc = sig_precise(gf) * g_c1[idx] + sig_precise(gi) * tanhf(gg);
                float hh = sig_precise(go) * tanhf(cc);
                g_c1[idx] = cc;
                g_h1[idx] = hh;
                g_xcatfch[b * 512 + j] = __float2half(hh);
            }
    }
    grid_barrier(&eps);

    // ===== P2: fc1+relu+Wfc2 partial (ctas 0-31) | dec_proj (ctas 32-63) =====
    if (cta < 32) {
        __shared__ float sfc[64][4];
        const int m0 = (cta & 7) * 64, n0 = (cta >> 3) * 64;
        gemm_mma_db(g_xcatfch, 512, g_Wfc1h, 512, m0, n0, 512, cf);
        float s0[2] = {0.f, 0.f}, s1[2] = {0.f, 0.f};
#pragma unroll
        for (int mt = 0; mt < 2; mt++)
#pragma unroll
            for (int nt = 0; nt < 2; nt++) {
                const int c = n0 + wn * 16 + (lane & 3) * 2 + nt * 8;
                const float b0 = bfc1[c], b1 = bfc1[c + 1];
                const float w0 = Wfc2[c], w1 = Wfc2[c + 1];
                s0[mt] += fmaxf(cf[mt][nt][0] + b0, 0.f) * w0 + fmaxf(cf[mt][nt][1] + b1, 0.f) * w1;
                s1[mt] += fmaxf(cf[mt][nt][2] + b0, 0.f) * w0 + fmaxf(cf[mt][nt][3] + b1, 0.f) * w1;
            }
#pragma unroll
        for (int off = 1; off < 4; off <<= 1) {
#pragma unroll
            for (int mt = 0; mt < 2; mt++) {
                s0[mt] += __shfl_xor_sync(0xffffffffu, s0[mt], off);
                s1[mt] += __shfl_xor_sync(0xffffffffu, s1[mt], off);
            }
        }
        if ((lane & 3) == 0) {
#pragma unroll
            for (int mt = 0; mt < 2; mt++) {
                int rl = wm * 32 + (lane >> 2) + mt * 16;
                sfc[rl][wn] = s0[mt];
                sfc[rl + 8][wn] = s1[mt];
            }
        }
        __syncthreads();
        if (tid < 64) {
            float p = sfc[tid][0] + sfc[tid][1] + sfc[tid][2] + sfc[tid][3];
            g_fcp4[(m0 + tid) * 4 + (cta >> 3)] = p;
        }
    } else if (cta < 64) {
        const int c2 = cta - 32;
        const int m0 = (c2 & 7) * 64, n0 = (c2 >> 3) * 64;
        gemm_mma_db(g_xcatfch, 512, g_Wt_dech, 256, m0, n0, 256, cf);
        const int erow = wm * 32 + (lane >> 2);
        const int ecol = wn * 16 + (lane & 3) * 2;
#pragma unroll
        for (int mt = 0; mt < 2; mt++)
#pragma unroll
            for (int nt = 0; nt < 2; nt++) {
                int r = m0 + erow + mt * 16, c = n0 + ecol + nt * 8;
                *(float2*)&g_dp[(size_t)r * AA + c] = make_float2(cf[mt][nt][0], cf[mt][nt][1]);
                *(float2*)&g_dp[(size_t)(r + 8) * AA + c] = make_float2(cf[mt][nt][2], cf[mt][nt][3]);
            }
    }
}

// ---------------- finalize last step's fc output ----------------
__global__ void finalize(const float* __restrict__ bfc2, float* __restrict__ outs) {
    int b = blockIdx.x * 256 + threadIdx.x;
    const float4 p = *(const float4*)&g_fcp4[b * 4];
    outs[b * TPRED + (TPRED - 1)] = (p.x + p.y) + (p.z + p.w) + bfc2[0];
}

// ---------------- initial dec_proj from encoder_hidden[1] ----------------
__global__ __launch_bounds__(256) void dp_init(const float* __restrict__ Wad) {
    __shared__ float sA[8][256];
    const int b0 = blockIdx.x * 8;
    const int tid = threadIdx.x;
#pragma unroll
    for (int q = 0; q < 2; q++) {
        int f4 = q * 256 + tid;
        int r = f4 >> 6, c = (f4 & 63) * 4;
        *(float4*)&sA[r][c] = *(const float4*)&g_h1[(size_t)(b0 + r) * 256 + c];
    }
    __syncthreads();
    float dpa[8];
#pragma unroll
    for (int r = 0; r < 8; r++) dpa[r] = 0.f;
#pragma unroll 4
    for (int h = 0; h < 256; h++) {
        const float wv = Wad[(size_t)h * AA + tid];
#pragma unroll
        for (int r = 0; r < 8; r++) dpa[r] = fmaf(sA[r][h], wv, dpa[r]);
    }
#pragma unroll
    for (int r = 0; r < 8; r++) g_dp[(b0 + r) * 256 + tid] = dpa[r];
}

// ---------------- host launcher ----------------
extern "C" void kernel_launch(void* const* d_in, const int* in_sizes, int n_in,
                              void* d_out, int out_size) {
    int off = (in_sizes[0] == 1) ? 1 : 0;
    const float* enc_out = (const float*)d_in[off + 0];
    const float* enc_h = (const float*)d_in[off + 1];
    const float* enc_c = (const float*)d_in[off + 2];
    const float* Wae = (const float*)d_in[off + 3];
    const float* Wad = (const float*)d_in[off + 4];
    const float* v = (const float*)d_in[off + 5];
    const float* Wih0 = (const float*)d_in[off + 6];
    const float* Whh0 = (const float*)d_in[off + 7];
    const float* bih0 = (const float*)d_in[off + 8];
    const float* bhh0 = (const float*)d_in[off + 9];
    const float* Wih1 = (const float*)d_in[off + 10];
    const float* Whh1 = (const float*)d_in[off + 11];
    const float* bih1 = (const float*)d_in[off + 12];
    const float* bhh1 = (const float*)d_in[off + 13];
    const float* Wfc1 = (const float*)d_in[off + 14];
    const float* bfc1 = (const float*)d_in[off + 15];
    const float* Wfc2 = (const float*)d_in[off + 16];
    const float* bfc2 = (const float*)d_in[off + 17];

    float* out = (float*)d_out;
    float* attn_base = out + (size_t)BB * TPRED;

    init_state<<<(BB * HH + 255) / 256, 256>>>(enc_h, enc_c);
    prep<<<2048, 256>>>(Wae, Wad, Wih0, Whh0, bih0, bhh0, Wih1, Whh1, bih1, bhh1, Wfc1);
    prep_eo<<<(BB * THIST * HENC / 4) / 256, 256>>>(enc_out);
    encproj_mma<<<dim3(4, 2048), 256>>>();
    dp_init<<<BB / 8, 256>>>(Wad);

    for (int s = 0; s < TPRED; s++) {
        attn_step<<<BB, 256>>>(v, attn_base + (size_t)s * BB * THIST, bfc2, out, s);
        recurrent_step<<<NCTAS, 256>>>(bfc1, Wfc2);
    }
    finalize<<<2, 256>>>(bfc2, out);
    (void)n_in;
    (void)out_size;
}

// round 16
// speedup vs baseline: 1.1352x; 1.0508x over previous
#include <cuda_runtime.h>
#include <cuda_fp16.h>
#include <cstdint>

#define BB 512
#define THIST 512
#define HENC 256
#define HH 256
#define AA 256
#define TPRED 32
#define NG 1024
#define NCTAS 128

// ---------------- device scratch (static only) ----------------
__device__ __half g_ep_h[(size_t)BB * THIST * AA];
__device__ __half g_eo_h[(size_t)BB * THIST * HENC];
__device__ __half g_Wt_ench[HENC * AA];
__device__ __half g_Wcat0rh[NG * 512];
__device__ __half g_Wcat1rh[NG * 512];
__device__ __half g_Wfc1h[HH * 512];
__device__ __half g_Wt_dech[AA * HH];
__device__ float g_wcol0r[NG];
__device__ float g_bias0r[NG];
__device__ float g_bias1r[NG];
__device__ float g_h0[BB * HH], g_h1[BB * HH];
__device__ float g_c0[BB * HH], g_c1[BB * HH];
__device__ float g_dec_in[BB];
__device__ float g_dp[BB * AA];
__device__ float g_fcp4[BB * 4];
__device__ __half g_xcat0h[BB * 512];
__device__ __half g_xcat1h[BB * 512];
__device__ __half g_xcatfch[BB * 512];

__device__ unsigned g_count = 0;
__device__ unsigned g_sense = 0;

// ---------------- helpers ----------------
__device__ __forceinline__ float ftanh_fast(float x) {
    float y;
    asm("tanh.approx.f32 %0, %1;" : "=f"(y) : "f"(x));
    return y;
}
__device__ __forceinline__ float sig_precise(float x) { return 1.f / (1.f + expf(-x)); }

__device__ __forceinline__ uint32_t smem_u32(const void* p) {
    uint32_t a;
    asm("{.reg .u64 t; cvta.to.shared.u64 t, %1; cvt.u32.u64 %0, t;}" : "=r"(a) : "l"(p));
    return a;
}
__device__ __forceinline__ void ldsm_x4(uint32_t addr, uint32_t& r0, uint32_t& r1,
                                        uint32_t& r2, uint32_t& r3) {
    asm volatile("ldmatrix.sync.aligned.m8n8.x4.shared.b16 {%0,%1,%2,%3}, [%4];"
                 : "=r"(r0), "=r"(r1), "=r"(r2), "=r"(r3) : "r"(addr));
}
__device__ __forceinline__ void ldsm_x2(uint32_t addr, uint32_t& r0, uint32_t& r1) {
    asm volatile("ldmatrix.sync.aligned.m8n8.x2.shared.b16 {%0,%1}, [%2];"
                 : "=r"(r0), "=r"(r1) : "r"(addr));
}
__device__ __forceinline__ void mma16816(float* d, uint32_t a0, uint32_t a1, uint32_t a2,
                                         uint32_t a3, uint32_t b0, uint32_t b1) {
    asm volatile(
        "mma.sync.aligned.m16n8k16.row.col.f32.f16.f16.f32 "
        "{%0,%1,%2,%3},{%4,%5,%6,%7},{%8,%9},{%0,%1,%2,%3};"
        : "+f"(d[0]), "+f"(d[1]), "+f"(d[2]), "+f"(d[3])
        : "r"(a0), "r"(a1), "r"(a2), "r"(a3), "r"(b0), "r"(b1));
}
__device__ __forceinline__ int4 ldcs_int4(const void* p) {
    int4 v;
    asm volatile("ld.global.cs.v4.b32 {%0,%1,%2,%3}, [%4];"
                 : "=r"(v.x), "=r"(v.y), "=r"(v.z), "=r"(v.w) : "l"(p));
    return v;
}

__device__ __forceinline__ void grid_barrier(unsigned* eps) {
    __syncthreads();
    if (threadIdx.x == 0) {
        unsigned target = ++(*eps);
        __threadfence();
        unsigned old = atomicAdd(&g_count, 1);
        if (old == NCTAS - 1) {
            g_count = 0;
            __threadfence();
            atomicExch(&g_sense, target);
        } else {
            while (atomicAdd(&g_sense, 0) != target) __nanosleep(64);
        }
    }
    __syncthreads();
}

// ---------------- init + prep ----------------
__global__ void init_state(const float* __restrict__ eh, const float* __restrict__ ec) {
    int i = blockIdx.x * blockDim.x + threadIdx.x;
    if (i < BB * HH) {
        g_h0[i] = eh[i];
        g_h1[i] = eh[BB * HH + i];
        g_c0[i] = ec[i];
        g_c1[i] = ec[BB * HH + i];
    }
    if (i < BB) g_dec_in[i] = 0.f;
}

__global__ void prep(const float* __restrict__ Wae, const float* __restrict__ Wad,
                     const float* __restrict__ Wih0, const float* __restrict__ Whh0,
                     const float* __restrict__ bih0, const float* __restrict__ bhh0,
                     const float* __restrict__ Wih1, const float* __restrict__ Whh1,
                     const float* __restrict__ bih1, const float* __restrict__ bhh1,
                     const float* __restrict__ Wfc1) {
    int i = blockIdx.x * blockDim.x + threadIdx.x;
    if (i < HENC * AA) {
        int a = i / HENC, e = i % HENC;
        g_Wt_ench[i] = __float2half(Wae[e * AA + a]);
    }
    if (i < NG * 512) {
        int n4 = i >> 9, c = i & 511;
        int j = n4 >> 2, g = n4 & 3;
        int n = g * 256 + j;
        g_Wcat0rh[i] = __float2half((c < 256) ? Wih0[n * 257 + 1 + c] : Whh0[n * 256 + (c - 256)]);
        g_Wcat1rh[i] = __float2half((c < 256) ? Wih1[n * 256 + c] : Whh1[n * 256 + (c - 256)]);
    }
    if (i < HH * 512) g_Wfc1h[i] = __float2half(Wfc1[i]);
    if (i < AA * HH) {
        int a = i >> 8, h = i & 255;
        g_Wt_dech[i] = __float2half(Wad[h * AA + a]);
    }
    if (i < NG) {
        int j = i >> 2, g = i & 3;
        int n = g * 256 + j;
        g_wcol0r[i] = Wih0[n * 257];
        g_bias0r[i] = bih0[n] + bhh0[n];
        g_bias1r[i] = bih1[n] + bhh1[n];
    }
}

__global__ void prep_eo(const float* __restrict__ eo) {
    int i = blockIdx.x * blockDim.x + threadIdx.x;
    const float4 v = ((const float4*)eo)[i];
    __half2 h[2] = {__floats2half2_rn(v.x, v.y), __floats2half2_rn(v.z, v.w)};
    ((uint2*)g_eo_h)[i] = *(uint2*)h;
}

// ---------------- enc_proj: single fp16 MMA, 128x64 tile, K-slab 64, double-buffered ----------------
__global__ __launch_bounds__(256) void encproj_mma() {
    __shared__ __half sA[2][128 * 72], sB[2][64 * 72];
    const int m0 = blockIdx.y * 128;
    const int n0 = blockIdx.x * 64;
    const int tid = threadIdx.x, lane = tid & 31, wid = tid >> 5;
    const int wm = wid & 3, wn = wid >> 2;
    float cf[2][4][4];
#pragma unroll
    for (int mt = 0; mt < 2; mt++)
#pragma unroll
        for (int nt = 0; nt < 4; nt++)
#pragma unroll
            for (int q = 0; q < 4; q++) cf[mt][nt][q] = 0.f;
    const int aRow = tid >> 1, aCol = (tid & 1) * 32;
    const int bRow = tid >> 2, bCol = (tid & 3) * 16;
    const uint32_t aB = smem_u32(sA), bB = smem_u32(sB);
    const int arow = wm * 32 + (lane & 15);
    const int acol8 = 8 * (lane >> 4);
    const int brow8 = (lane & 7);
    const int bcol8 = 8 * ((lane >> 3) & 1);

    uint4 ra[4], rb[2];
#pragma unroll
    for (int q = 0; q < 4; q++)
        ra[q] = *(const uint4*)&g_eo_h[(size_t)(m0 + aRow) * 256 + aCol + q * 8];
#pragma unroll
    for (int q = 0; q < 2; q++)
        rb[q] = *(const uint4*)&g_Wt_ench[(size_t)(n0 + bRow) * 256 + bCol + q * 8];
#pragma unroll
    for (int it = 0; it < 4; it++) {
        const int buf = it & 1;
#pragma unroll
        for (int q = 0; q < 4; q++) *(uint4*)&sA[buf][aRow * 72 + aCol + q * 8] = ra[q];
#pragma unroll
        for (int q = 0; q < 2; q++) *(uint4*)&sB[buf][bRow * 72 + bCol + q * 8] = rb[q];
        __syncthreads();
        if (it < 3) {
            const int kc = (it + 1) * 64;
#pragma unroll
            for (int q = 0; q < 4; q++)
                ra[q] = *(const uint4*)&g_eo_h[(size_t)(m0 + aRow) * 256 + kc + aCol + q * 8];
#pragma unroll
            for (int q = 0; q < 2; q++)
                rb[q] = *(const uint4*)&g_Wt_ench[(size_t)(n0 + bRow) * 256 + kc + bCol + q * 8];
        }
        const uint32_t offA = buf * (128 * 72) * 2;
        const uint32_t offB = buf * (64 * 72) * 2;
#pragma unroll
        for (int ks = 0; ks < 64; ks += 16) {
            uint32_t a[2][4], b[4][2];
#pragma unroll
            for (int mt = 0; mt < 2; mt++)
                ldsm_x4(aB + offA + ((arow + mt * 16) * 72 + ks + acol8) * 2,
                        a[mt][0], a[mt][1], a[mt][2], a[mt][3]);
#pragma unroll
            for (int nt = 0; nt < 4; nt++)
                ldsm_x2(bB + offB + ((wn * 32 + nt * 8 + brow8) * 72 + ks + bcol8) * 2,
                        b[nt][0], b[nt][1]);
#pragma unroll
            for (int mt = 0; mt < 2; mt++)
#pragma unroll
                for (int nt = 0; nt < 4; nt++)
                    mma16816(cf[mt][nt], a[mt][0], a[mt][1], a[mt][2], a[mt][3],
                             b[nt][0], b[nt][1]);
        }
    }
    const int erow = wm * 32 + (lane >> 2);
    const int ecol0 = wn * 32 + (lane & 3) * 2;
#pragma unroll
    for (int mt = 0; mt < 2; mt++)
#pragma unroll
        for (int nt = 0; nt < 4; nt++) {
            int r = m0 + erow + mt * 16, c = n0 + ecol0 + nt * 8;
            *(__half2*)&g_ep_h[(size_t)r * AA + c] = __floats2half2_rn(cf[mt][nt][0], cf[mt][nt][1]);
            *(__half2*)&g_ep_h[(size_t)(r + 8) * AA + c] = __floats2half2_rn(cf[mt][nt][2], cf[mt][nt][3]);
        }
}

// ---------------- fused attention (per step) + prev-step fc2 finalize ----------------
// 4 CTAs/SM forced: all 512 CTAs co-resident (no wave tail). 4 rows in flight.
__global__ __launch_bounds__(256, 4) void attn_step(const float* __restrict__ v,
                                                    float* __restrict__ attn_out,
                                                    const float* __restrict__ bfc2,
                                                    float* __restrict__ outs, int s) {
    __shared__ float s_dp[256];
    __shared__ float s_v[256];
    __shared__ float s_sc[512];
    __shared__ float s_red[8];
    __shared__ float s_ctx[8][256];
    const int b = blockIdx.x;
    const int tid = threadIdx.x;
    const int lane = tid & 31, w = tid >> 5;

    if (s > 0 && tid == 0) {
        const float4 p = *(const float4*)&g_fcp4[b * 4];
        float o = (p.x + p.y) + (p.z + p.w) + bfc2[0];
        outs[b * TPRED + (s - 1)] = o;
        g_dec_in[b] = o;
    }

    s_dp[tid] = g_dp[b * 256 + tid];
    s_v[tid] = v[tid];
    __syncthreads();

    float vr[8], dr[8];
#pragma unroll
    for (int i = 0; i < 8; i++) {
        vr[i] = s_v[lane * 8 + i];
        dr[i] = s_dp[lane * 8 + i];
    }

    // ---- scores: 4 rows in flight (same per-row FMA order as before) ----
    const __half* ep = g_ep_h + (size_t)b * THIST * AA;
    for (int i0 = 0; i0 < 64; i0 += 4) {
        int4 raw[4];
#pragma unroll
        for (int u = 0; u < 4; u++) {
            int t = w + (i0 + u) * 8;
            raw[u] = ldcs_int4(ep + (size_t)t * AA + lane * 8);
        }
        float ss[4];
#pragma unroll
        for (int u = 0; u < 4; u++) {
            const __half2* hp = (const __half2*)&raw[u];
            float acc = 0.f;
#pragma unroll
            for (int q = 0; q < 4; q++) {
                float2 f = __half22float2(hp[q]);
                acc = fmaf(vr[2 * q + 0], ftanh_fast(f.x + dr[2 * q + 0]), acc);
                acc = fmaf(vr[2 * q + 1], ftanh_fast(f.y + dr[2 * q + 1]), acc);
            }
            ss[u] = acc;
        }
#pragma unroll
        for (int off = 16; off; off >>= 1)
#pragma unroll
            for (int u = 0; u < 4; u++) ss[u] += __shfl_xor_sync(0xffffffffu, ss[u], off);
        if (lane == 0) {
#pragma unroll
            for (int u = 0; u < 4; u++) s_sc[w + (i0 + u) * 8] = ss[u];
        }
    }
    __syncthreads();

    float m = fmaxf(s_sc[tid], s_sc[tid + 256]);
#pragma unroll
    for (int off = 16; off; off >>= 1) m = fmaxf(m, __shfl_xor_sync(0xffffffffu, m, off));
    if (lane == 0) s_red[w] = m;
    __syncthreads();
    float mm = s_red[0];
#pragma unroll
    for (int i = 1; i < 8; i++) mm = fmaxf(mm, s_red[i]);
    float e0 = __expf(s_sc[tid] - mm);
    float e1 = __expf(s_sc[tid + 256] - mm);
    float sm = e0 + e1;
#pragma unroll
    for (int off = 16; off; off >>= 1) sm += __shfl_xor_sync(0xffffffffu, sm, off);
    __syncthreads();
    if (lane == 0) s_red[w] = sm;
    __syncthreads();
    float tot = s_red[0];
#pragma unroll
    for (int i = 1; i < 8; i++) tot += s_red[i];
    float inv = 1.f / tot;
    float p0 = e0 * inv, p1 = e1 * inv;
    s_sc[tid] = p0;
    s_sc[tid + 256] = p1;
    attn_out[(size_t)b * THIST + tid] = p0;
    attn_out[(size_t)b * THIST + tid + 256] = p1;
    __syncthreads();

    // ---- ctx: 4 rows in flight (same per-lane accumulation order) ----
    const __half* eob = g_eo_h + (size_t)b * THIST * HENC;
    float cacc[8];
#pragma unroll
    for (int q = 0; q < 8; q++) cacc[q] = 0.f;
    for (int i0 = 0; i0 < 64; i0 += 4) {
        int4 r[4];
        float p[4];
#pragma unroll
        for (int u = 0; u < 4; u++) {
            int t = w + (i0 + u) * 8;
            r[u] = ldcs_int4(eob + (size_t)t * HENC + lane * 8);
            p[u] = s_sc[t];
        }
#pragma unroll
        for (int u = 0; u < 4; u++) {
            const __half2* hp = (const __half2*)&r[u];
#pragma unroll
            for (int q = 0; q < 4; q++) {
                float2 f = __half22float2(hp[q]);
                cacc[2 * q + 0] = fmaf(p[u], f.x, cacc[2 * q + 0]);
                cacc[2 * q + 1] = fmaf(p[u], f.y, cacc[2 * q + 1]);
            }
        }
    }
#pragma unroll
    for (int q = 0; q < 8; q++) s_ctx[w][lane * 8 + q] = cacc[q];
    __syncthreads();

    const int e = tid;
    float csum = 0.f;
#pragma unroll
    for (int q = 0; q < 8; q++) csum += s_ctx[q][e];
    g_xcat0h[b * 512 + e] = __float2half(csum);
    g_xcat0h[b * 512 + 256 + e] = __float2half(g_h0[b * 256 + e]);
    g_xcatfch[b * 512 + 256 + e] = __float2half(csum);
}

// ---------------- double-buffered fp16 MMA 64x64 tile GEMM core, K-slab 64 ----------------
__device__ void gemm_mma_db(const __half* __restrict__ A, int lda,
                            const __half* __restrict__ B, int ldb,
                            int m0, int n0, int ktot, float cf[2][2][4]) {
    static __shared__ __half sA[2][64 * 72];
    static __shared__ __half sB[2][64 * 72];
    const int tid = threadIdx.x, lane = tid & 31, wid = tid >> 5;
    const int wm = wid & 1, wn = wid >> 1;
#pragma unroll
    for (int mt = 0; mt < 2; mt++)
#pragma unroll
        for (int nt = 0; nt < 2; nt++)
#pragma unroll
            for (int q = 0; q < 4; q++) cf[mt][nt][q] = 0.f;
    const int lrow = tid >> 2, lcol = (tid & 3) * 16;
    const uint32_t aBase = smem_u32(sA), bBase = smem_u32(sB);
    const int arow = wm * 32 + (lane & 15);
    const int acol8 = 8 * (lane >> 4);
    const int brow = wn * 16 + (lane & 7);
    const int bcol8 = 8 * ((lane >> 3) & 1);
    const int niter = ktot / 64;

    uint4 ra0 = *(const uint4*)&A[(size_t)(m0 + lrow) * lda + lcol];
    uint4 ra1 = *(const uint4*)&A[(size_t)(m0 + lrow) * lda + lcol + 8];
    uint4 rb0 = *(const uint4*)&B[(size_t)(n0 + lrow) * ldb + lcol];
    uint4 rb1 = *(const uint4*)&B[(size_t)(n0 + lrow) * ldb + lcol + 8];
    for (int it = 0; it < niter; it++) {
        const int buf = it & 1;
        *(uint4*)&sA[buf][lrow * 72 + lcol] = ra0;
        *(uint4*)&sA[buf][lrow * 72 + lcol + 8] = ra1;
        *(uint4*)&sB[buf][lrow * 72 + lcol] = rb0;
        *(uint4*)&sB[buf][lrow * 72 + lcol + 8] = rb1;
        __syncthreads();
        if (it + 1 < niter) {
            const int kc = (it + 1) * 64;
            ra0 = *(const uint4*)&A[(size_t)(m0 + lrow) * lda + kc + lcol];
            ra1 = *(const uint4*)&A[(size_t)(m0 + lrow) * lda + kc + lcol + 8];
            rb0 = *(const uint4*)&B[(size_t)(n0 + lrow) * ldb + kc + lcol];
            rb1 = *(const uint4*)&B[(size_t)(n0 + lrow) * ldb + kc + lcol + 8];
        }
        const uint32_t off = buf * (64 * 72) * 2;
#pragma unroll
        for (int ks = 0; ks < 64; ks += 16) {
            uint32_t a[2][4], bfrag[2][2];
#pragma unroll
            for (int mt = 0; mt < 2; mt++)
                ldsm_x4(aBase + off + ((arow + mt * 16) * 72 + ks + acol8) * 2,
                        a[mt][0], a[mt][1], a[mt][2], a[mt][3]);
#pragma unroll
            for (int nt = 0; nt < 2; nt++)
                ldsm_x2(bBase + off + ((brow + nt * 8) * 72 + ks + bcol8) * 2,
                        bfrag[nt][0], bfrag[nt][1]);
#pragma unroll
            for (int mt = 0; mt < 2; mt++)
#pragma unroll
                for (int nt = 0; nt < 2; nt++)
                    mma16816(cf[mt][nt], a[mt][0], a[mt][1], a[mt][2], a[mt][3],
                             bfrag[nt][0], bfrag[nt][1]);
        }
    }
}

// ---------------- fused recurrent step: 3 phases, 2 barriers ----------------
__global__ __launch_bounds__(256) void recurrent_step(const float* __restrict__ bfc1,
                                                      const float* __restrict__ Wfc2) {
    unsigned eps = 0;
    if (threadIdx.x == 0) eps = atomicAdd(&g_sense, 0);
    const int cta = blockIdx.x;
    const int tid = threadIdx.x;
    const int lane = tid & 31, wid = tid >> 5;
    const int wm = wid & 1, wn = wid >> 1;
    const int parity = lane & 1;
    float cf[2][2][4];

    // ===== P0: lstm0 gates GEMM + cell0 epilogue =====
    {
        const int m0 = (cta & 7) * 64, n0 = (cta >> 3) * 64;
        gemm_mma_db(g_xcat0h, 512, g_Wcat0rh, 512, m0, n0, 512, cf);
#pragma unroll
        for (int mt = 0; mt < 2; mt++)
#pragma unroll
            for (int nt = 0; nt < 2; nt++) {
                float t0 = __shfl_xor_sync(0xffffffffu, cf[mt][nt][0], 1);
                float t1 = __shfl_xor_sync(0xffffffffu, cf[mt][nt][1], 1);
                float t2 = __shfl_xor_sync(0xffffffffu, cf[mt][nt][2], 1);
                float t3 = __shfl_xor_sync(0xffffffffu, cf[mt][nt][3], 1);
                const int c = n0 + wn * 16 + (lane & 3) * 2 + nt * 8;
                const int j = c >> 2;
                const int r = m0 + wm * 32 + (lane >> 2) + mt * 16;
                int b;
                float gi, gf, gg, go;
                if (!parity) { b = r;     gi = cf[mt][nt][0]; gf = cf[mt][nt][1]; gg = t0; go = t1; }
                else         { b = r + 8; gi = t2;            gf = t3;            gg = cf[mt][nt][2]; go = cf[mt][nt][3]; }
                const float din = g_dec_in[b];
                const float4 wc = *(const float4*)&g_wcol0r[4 * j];
                const float4 bs = *(const float4*)&g_bias0r[4 * j];
                gi += din * wc.x + bs.x;
                gf += din * wc.y + bs.y;
                gg += din * wc.z + bs.z;
                go += din * wc.w + bs.w;
                const int idx = b * 256 + j;
                float cc = sig_precise(gf) * g_c0[idx] + sig_precise(gi) * tanhf(gg);
                float hh = sig_precise(go) * tanhf(cc);
                g_c0[idx] = cc;
                g_h0[idx] = hh;
                g_xcat1h[b * 512 + j] = __float2half(hh);
                g_xcat1h[b * 512 + 256 + j] = __float2half(g_h1[idx]);
            }
    }
    grid_barrier(&eps);

    // ===== P1: lstm1 gates GEMM + cell1 epilogue =====
    {
        const int m0 = (cta & 7) * 64, n0 = (cta >> 3) * 64;
        gemm_mma_db(g_xcat1h, 512, g_Wcat1rh, 512, m0, n0, 512, cf);
#pragma unroll
        for (int mt = 0; mt < 2; mt++)
#pragma unroll
            for (int nt = 0; nt < 2; nt++) {
                float t0 = __shfl_xor_sync(0xffffffffu, cf[mt][nt][0], 1);
                float t1 = __shfl_xor_sync(0xffffffffu, cf[mt][nt][1], 1);
                float t2 = __shfl_xor_sync(0xffffffffu, cf[mt][nt][2], 1);
                float t3 = __shfl_xor_sync(0xffffffffu, cf[mt][nt][3], 1);
                const int c = n0 + wn * 16 + (lane & 3) * 2 + nt * 8;
                const int j = c >> 2;
                const int r = m0 + wm * 32 + (lane >> 2) + mt * 16;
                int b;
                float gi, gf, gg, go;
                if (!parity) { b = r;     gi = cf[mt][nt][0]; gf = cf[mt][nt][1]; gg = t0; go = t1; }
                else         { b = r + 8; gi = t2;            gf = t3;            gg = cf[mt][nt][2]; go = cf[mt][nt][3]; }
                const float4 bs = *(const float4*)&g_bias1r[4 * j];
                gi += bs.x;
                gf += bs.y;
                gg += bs.z;
                go += bs.w;
                const int idx = b * 256 + j;
                float cc = sig_precise(gf) * g_c1[idx] + sig_precise(gi) * tanhf(gg);
                float hh = sig_precise(go) * tanhf(cc);
                g_c1[idx] = cc;
                g_h1[idx] = hh;
                g_xcatfch[b * 512 + j] = __float2half(hh);
            }
    }
    grid_barrier(&eps);

    // ===== P2: fc1+relu+Wfc2 partial (ctas 0-31) | dec_proj (ctas 32-63) =====
    if (cta < 32) {
        __shared__ float sfc[64][4];
        const int m0 = (cta & 7) * 64, n0 = (cta >> 3) * 64;
        gemm_mma_db(g_xcatfch, 512, g_Wfc1h, 512, m0, n0, 512, cf);
        float s0[2] = {0.f, 0.f}, s1[2] = {0.f, 0.f};
#pragma unroll
        for (int mt = 0; mt < 2; mt++)
#pragma unroll
            for (int nt = 0; nt < 2; nt++) {
                const int c = n0 + wn * 16 + (lane & 3) * 2 + nt * 8;
                const float b0 = bfc1[c], b1 = bfc1[c + 1];
                const float w0 = Wfc2[c], w1 = Wfc2[c + 1];
                s0[mt] += fmaxf(cf[mt][nt][0] + b0, 0.f) * w0 + fmaxf(cf[mt][nt][1] + b1, 0.f) * w1;
                s1[mt] += fmaxf(cf[mt][nt][2] + b0, 0.f) * w0 + fmaxf(cf[mt][nt][3] + b1, 0.f) * w1;
            }
#pragma unroll
        for (int off = 1; off < 4; off <<= 1) {
#pragma unroll
            for (int mt = 0; mt < 2; mt++) {
                s0[mt] += __shfl_xor_sync(0xffffffffu, s0[mt], off);
                s1[mt] += __shfl_xor_sync(0xffffffffu, s1[mt], off);
            }
        }
        if ((lane & 3) == 0) {
#pragma unroll
            for (int mt = 0; mt < 2; mt++) {
                int rl = wm * 32 + (lane >> 2) + mt * 16;
                sfc[rl][wn] = s0[mt];
                sfc[rl + 8][wn] = s1[mt];
            }
        }
        __syncthreads();
        if (tid < 64) {
            float p = sfc[tid][0] + sfc[tid][1] + sfc[tid][2] + sfc[tid][3];
            g_fcp4[(m0 + tid) * 4 + (cta >> 3)] = p;
        }
    } else if (cta < 64) {
        const int c2 = cta - 32;
        const int m0 = (c2 & 7) * 64, n0 = (c2 >> 3) * 64;
        gemm_mma_db(g_xcatfch, 512, g_Wt_dech, 256, m0, n0, 256, cf);
        const int erow = wm * 32 + (lane >> 2);
        const int ecol = wn * 16 + (lane & 3) * 2;
#pragma unroll
        for (int mt = 0; mt < 2; mt++)
#pragma unroll
            for (int nt = 0; nt < 2; nt++) {
                int r = m0 + erow + mt * 16, c = n0 + ecol + nt * 8;
                *(float2*)&g_dp[(size_t)r * AA + c] = make_float2(cf[mt][nt][0], cf[mt][nt][1]);
                *(float2*)&g_dp[(size_t)(r + 8) * AA + c] = make_float2(cf[mt][nt][2], cf[mt][nt][3]);
            }
    }
}

// ---------------- finalize last step's fc output ----------------
__global__ void finalize(const float* __restrict__ bfc2, float* __restrict__ outs) {
    int b = blockIdx.x * 256 + threadIdx.x;
    const float4 p = *(const float4*)&g_fcp4[b * 4];
    outs[b * TPRED + (TPRED - 1)] = (p.x + p.y) + (p.z + p.w) + bfc2[0];
}

// ---------------- initial dec_proj from encoder_hidden[1] ----------------
__global__ __launch_bounds__(256) void dp_init(const float* __restrict__ Wad) {
    __shared__ float sA[8][256];
    const int b0 = blockIdx.x * 8;
    const int tid = threadIdx.x;
#pragma unroll
    for (int q = 0; q < 2; q++) {
        int f4 = q * 256 + tid;
        int r = f4 >> 6, c = (f4 & 63) * 4;
        *(float4*)&sA[r][c] = *(const float4*)&g_h1[(size_t)(b0 + r) * 256 + c];
    }
    __syncthreads();
    float dpa[8];
#pragma unroll
    for (int r = 0; r < 8; r++) dpa[r] = 0.f;
#pragma unroll 4
    for (int h = 0; h < 256; h++) {
        const float wv = Wad[(size_t)h * AA + tid];
#pragma unroll
        for (int r = 0; r < 8; r++) dpa[r] = fmaf(sA[r][h], wv, dpa[r]);
    }
#pragma unroll
    for (int r = 0; r < 8; r++) g_dp[(b0 + r) * 256 + tid] = dpa[r];
}

// ---------------- host launcher ----------------
extern "C" void kernel_launch(void* const* d_in, const int* in_sizes, int n_in,
                              void* d_out, int out_size) {
    int off = (in_sizes[0] == 1) ? 1 : 0;
    const float* enc_out = (const float*)d_in[off + 0];
    const float* enc_h = (const float*)d_in[off + 1];
    const float* enc_c = (const float*)d_in[off + 2];
    const float* Wae = (const float*)d_in[off + 3];
    const float* Wad = (const float*)d_in[off + 4];
    const float* v = (const float*)d_in[off + 5];
    const float* Wih0 = (const float*)d_in[off + 6];
    const float* Whh0 = (const float*)d_in[off + 7];
    const float* bih0 = (const float*)d_in[off + 8];
    const float* bhh0 = (const float*)d_in[off + 9];
    const float* Wih1 = (const float*)d_in[off + 10];
    const float* Whh1 = (const float*)d_in[off + 11];
    const float* bih1 = (const float*)d_in[off + 12];
    const float* bhh1 = (const float*)d_in[off + 13];
    const float* Wfc1 = (const float*)d_in[off + 14];
    const float* bfc1 = (const float*)d_in[off + 15];
    const float* Wfc2 = (const float*)d_in[off + 16];
    const float* bfc2 = (const float*)d_in[off + 17];

    float* out = (float*)d_out;
    float* attn_base = out + (size_t)BB * TPRED;

    init_state<<<(BB * HH + 255) / 256, 256>>>(enc_h, enc_c);
    prep<<<2048, 256>>>(Wae, Wad, Wih0, Whh0, bih0, bhh0, Wih1, Whh1, bih1, bhh1, Wfc1);
    prep_eo<<<(BB * THIST * HENC / 4) / 256, 256>>>(enc_out);
    encproj_mma<<<dim3(4, 2048), 256>>>();
    dp_init<<<BB / 8, 256>>>(Wad);

    for (int s = 0; s < TPRED; s++) {
        attn_step<<<BB, 256>>>(v, attn_base + (size_t)s * BB * THIST, bfc2, out, s);
        recurrent_step<<<NCTAS, 256>>>(bfc1, Wfc2);
    }
    finalize<<<2, 256>>>(bfc2, out);
    (void)n_in;
    (void)out_size;
}

// round 17
// speedup vs baseline: 1.1411x; 1.0053x over previous
#include <cuda_runtime.h>
#include <cuda_fp16.h>
#include <cstdint>

#define BB 512
#define THIST 512
#define HENC 256
#define HH 256
#define AA 256
#define TPRED 32
#define NG 1024
#define NCTAS 128

// ---------------- device scratch (static only) ----------------
__device__ __half g_ep_h[(size_t)BB * THIST * AA];
__device__ __half g_eo_h[(size_t)BB * THIST * HENC];
__device__ __half g_Wt_ench[HENC * AA];
__device__ __half g_Wcat0rh[NG * 512];
__device__ __half g_Wcat1rh[NG * 512];
__device__ __half g_Wfc1h[HH * 512];
__device__ __half g_Wt_dech[AA * HH];
__device__ float g_wcol0r[NG];
__device__ float g_bias0r[NG];
__device__ float g_bias1r[NG];
__device__ float g_h0[BB * HH], g_h1[BB * HH];
__device__ float g_c0[BB * HH], g_c1[BB * HH];
__device__ float g_dec_in[BB];
__device__ float g_dp[BB * AA];
__device__ float g_fcp4[BB * 4];
__device__ __half g_xcat0h[BB * 512];
__device__ __half g_xcat1h[BB * 512];
__device__ __half g_xcatfch[BB * 512];

__device__ unsigned g_count = 0;
__device__ unsigned g_sense = 0;

// ---------------- helpers ----------------
__device__ __forceinline__ float ftanh_fast(float x) {
    float y;
    asm("tanh.approx.f32 %0, %1;" : "=f"(y) : "f"(x));
    return y;
}
__device__ __forceinline__ float sig_precise(float x) { return 1.f / (1.f + expf(-x)); }

__device__ __forceinline__ uint32_t smem_u32(const void* p) {
    uint32_t a;
    asm("{.reg .u64 t; cvta.to.shared.u64 t, %1; cvt.u32.u64 %0, t;}" : "=r"(a) : "l"(p));
    return a;
}
__device__ __forceinline__ void ldsm_x4(uint32_t addr, uint32_t& r0, uint32_t& r1,
                                        uint32_t& r2, uint32_t& r3) {
    asm volatile("ldmatrix.sync.aligned.m8n8.x4.shared.b16 {%0,%1,%2,%3}, [%4];"
                 : "=r"(r0), "=r"(r1), "=r"(r2), "=r"(r3) : "r"(addr));
}
__device__ __forceinline__ void ldsm_x2(uint32_t addr, uint32_t& r0, uint32_t& r1) {
    asm volatile("ldmatrix.sync.aligned.m8n8.x2.shared.b16 {%0,%1}, [%2];"
                 : "=r"(r0), "=r"(r1) : "r"(addr));
}
__device__ __forceinline__ void mma16816(float* d, uint32_t a0, uint32_t a1, uint32_t a2,
                                         uint32_t a3, uint32_t b0, uint32_t b1) {
    asm volatile(
        "mma.sync.aligned.m16n8k16.row.col.f32.f16.f16.f32 "
        "{%0,%1,%2,%3},{%4,%5,%6,%7},{%8,%9},{%0,%1,%2,%3};"
        : "+f"(d[0]), "+f"(d[1]), "+f"(d[2]), "+f"(d[3])
        : "r"(a0), "r"(a1), "r"(a2), "r"(a3), "r"(b0), "r"(b1));
}
__device__ __forceinline__ int4 ldcs_int4(const void* p) {
    int4 v;
    asm volatile("ld.global.cs.v4.b32 {%0,%1,%2,%3}, [%4];"
                 : "=r"(v.x), "=r"(v.y), "=r"(v.z), "=r"(v.w) : "l"(p));
    return v;
}
__device__ __forceinline__ void stcs_f(float* p, float v) {
    asm volatile("st.global.cs.f32 [%0], %1;" :: "l"(p), "f"(v) : "memory");
}
__device__ __forceinline__ void stcs_u32(void* p, uint32_t v) {
    asm volatile("st.global.cs.b32 [%0], %1;" :: "l"(p), "r"(v) : "memory");
}

__device__ __forceinline__ void grid_barrier(unsigned* eps) {
    __syncthreads();
    if (threadIdx.x == 0) {
        unsigned target = ++(*eps);
        __threadfence();
        unsigned old = atomicAdd(&g_count, 1);
        if (old == NCTAS - 1) {
            g_count = 0;
            __threadfence();
            atomicExch(&g_sense, target);
        } else {
            while (atomicAdd(&g_sense, 0) != target) __nanosleep(64);
        }
    }
    __syncthreads();
}

// ---------------- init + prep ----------------
__global__ void init_state(const float* __restrict__ eh, const float* __restrict__ ec) {
    int i = blockIdx.x * blockDim.x + threadIdx.x;
    if (i < BB * HH) {
        g_h0[i] = eh[i];
        g_h1[i] = eh[BB * HH + i];
        g_c0[i] = ec[i];
        g_c1[i] = ec[BB * HH + i];
    }
    if (i < BB) g_dec_in[i] = 0.f;
}

__global__ void prep(const float* __restrict__ Wae, const float* __restrict__ Wad,
                     const float* __restrict__ Wih0, const float* __restrict__ Whh0,
                     const float* __restrict__ bih0, const float* __restrict__ bhh0,
                     const float* __restrict__ Wih1, const float* __restrict__ Whh1,
                     const float* __restrict__ bih1, const float* __restrict__ bhh1,
                     const float* __restrict__ Wfc1) {
    int i = blockIdx.x * blockDim.x + threadIdx.x;
    if (i < HENC * AA) {
        int a = i / HENC, e = i % HENC;
        g_Wt_ench[i] = __float2half(Wae[e * AA + a]);
    }
    if (i < NG * 512) {
        int n4 = i >> 9, c = i & 511;
        int j = n4 >> 2, g = n4 & 3;
        int n = g * 256 + j;
        g_Wcat0rh[i] = __float2half((c < 256) ? Wih0[n * 257 + 1 + c] : Whh0[n * 256 + (c - 256)]);
        g_Wcat1rh[i] = __float2half((c < 256) ? Wih1[n * 256 + c] : Whh1[n * 256 + (c - 256)]);
    }
    if (i < HH * 512) g_Wfc1h[i] = __float2half(Wfc1[i]);
    if (i < AA * HH) {
        int a = i >> 8, h = i & 255;
        g_Wt_dech[i] = __float2half(Wad[h * AA + a]);
    }
    if (i < NG) {
        int j = i >> 2, g = i & 3;
        int n = g * 256 + j;
        g_wcol0r[i] = Wih0[n * 257];
        g_bias0r[i] = bih0[n] + bhh0[n];
        g_bias1r[i] = bih1[n] + bhh1[n];
    }
}

__global__ void prep_eo(const float* __restrict__ eo) {
    int i = blockIdx.x * blockDim.x + threadIdx.x;
    const int4 raw = ldcs_int4((const int4*)eo + i);
    const float4 v = *(const float4*)&raw;
    __half2 h[2] = {__floats2half2_rn(v.x, v.y), __floats2half2_rn(v.z, v.w)};
    ((uint2*)g_eo_h)[i] = *(uint2*)h;
}

// ---------------- enc_proj: single fp16 MMA, 128x64 tile, K-slab 64, double-buffered ----------------
__global__ __launch_bounds__(256) void encproj_mma() {
    __shared__ __half sA[2][128 * 72], sB[2][64 * 72];
    const int m0 = blockIdx.y * 128;
    const int n0 = blockIdx.x * 64;
    const int tid = threadIdx.x, lane = tid & 31, wid = tid >> 5;
    const int wm = wid & 3, wn = wid >> 2;
    float cf[2][4][4];
#pragma unroll
    for (int mt = 0; mt < 2; mt++)
#pragma unroll
        for (int nt = 0; nt < 4; nt++)
#pragma unroll
            for (int q = 0; q < 4; q++) cf[mt][nt][q] = 0.f;
    const int aRow = tid >> 1, aCol = (tid & 1) * 32;
    const int bRow = tid >> 2, bCol = (tid & 3) * 16;
    const uint32_t aB = smem_u32(sA), bB = smem_u32(sB);
    const int arow = wm * 32 + (lane & 15);
    const int acol8 = 8 * (lane >> 4);
    const int brow8 = (lane & 7);
    const int bcol8 = 8 * ((lane >> 3) & 1);

    uint4 ra[4], rb[2];
#pragma unroll
    for (int q = 0; q < 4; q++)
        ra[q] = *(const uint4*)&g_eo_h[(size_t)(m0 + aRow) * 256 + aCol + q * 8];
#pragma unroll
    for (int q = 0; q < 2; q++)
        rb[q] = *(const uint4*)&g_Wt_ench[(size_t)(n0 + bRow) * 256 + bCol + q * 8];
#pragma unroll
    for (int it = 0; it < 4; it++) {
        const int buf = it & 1;
#pragma unroll
        for (int q = 0; q < 4; q++) *(uint4*)&sA[buf][aRow * 72 + aCol + q * 8] = ra[q];
#pragma unroll
        for (int q = 0; q < 2; q++) *(uint4*)&sB[buf][bRow * 72 + bCol + q * 8] = rb[q];
        __syncthreads();
        if (it < 3) {
            const int kc = (it + 1) * 64;
#pragma unroll
            for (int q = 0; q < 4; q++)
                ra[q] = *(const uint4*)&g_eo_h[(size_t)(m0 + aRow) * 256 + kc + aCol + q * 8];
#pragma unroll
            for (int q = 0; q < 2; q++)
                rb[q] = *(const uint4*)&g_Wt_ench[(size_t)(n0 + bRow) * 256 + kc + bCol + q * 8];
        }
        const uint32_t offA = buf * (128 * 72) * 2;
        const uint32_t offB = buf * (64 * 72) * 2;
#pragma unroll
        for (int ks = 0; ks < 64; ks += 16) {
            uint32_t a[2][4], b[4][2];
#pragma unroll
            for (int mt = 0; mt < 2; mt++)
                ldsm_x4(aB + offA + ((arow + mt * 16) * 72 + ks + acol8) * 2,
                        a[mt][0], a[mt][1], a[mt][2], a[mt][3]);
#pragma unroll
            for (int nt = 0; nt < 4; nt++)
                ldsm_x2(bB + offB + ((wn * 32 + nt * 8 + brow8) * 72 + ks + bcol8) * 2,
                        b[nt][0], b[nt][1]);
#pragma unroll
            for (int mt = 0; mt < 2; mt++)
#pragma unroll
                for (int nt = 0; nt < 4; nt++)
                    mma16816(cf[mt][nt], a[mt][0], a[mt][1], a[mt][2], a[mt][3],
                             b[nt][0], b[nt][1]);
        }
    }
    const int erow = wm * 32 + (lane >> 2);
    const int ecol0 = wn * 32 + (lane & 3) * 2;
#pragma unroll
    for (int mt = 0; mt < 2; mt++)
#pragma unroll
        for (int nt = 0; nt < 4; nt++) {
            int r = m0 + erow + mt * 16, c = n0 + ecol0 + nt * 8;
            __half2 h0 = __floats2half2_rn(cf[mt][nt][0], cf[mt][nt][1]);
            __half2 h1 = __floats2half2_rn(cf[mt][nt][2], cf[mt][nt][3]);
            stcs_u32(&g_ep_h[(size_t)r * AA + c], *(uint32_t*)&h0);
            stcs_u32(&g_ep_h[(size_t)(r + 8) * AA + c], *(uint32_t*)&h1);
        }
}

// ---------------- fused attention (per step) + prev-step fc2 finalize ----------------
__global__ __launch_bounds__(256, 4) void attn_step(const float* __restrict__ v,
                                                    float* __restrict__ attn_out,
                                                    const float* __restrict__ bfc2,
                                                    float* __restrict__ outs, int s) {
    __shared__ float s_dp[256];
    __shared__ float s_v[256];
    __shared__ float s_sc[512];
    __shared__ float s_red[8];
    __shared__ float s_ctx[8][256];
    const int b = blockIdx.x;
    const int tid = threadIdx.x;
    const int lane = tid & 31, w = tid >> 5;

    if (s > 0 && tid == 0) {
        const float4 p = *(const float4*)&g_fcp4[b * 4];
        float o = (p.x + p.y) + (p.z + p.w) + bfc2[0];
        outs[b * TPRED + (s - 1)] = o;
        g_dec_in[b] = o;
    }

    s_dp[tid] = g_dp[b * 256 + tid];
    s_v[tid] = v[tid];
    __syncthreads();

    float vr[8], dr[8];
#pragma unroll
    for (int i = 0; i < 8; i++) {
        vr[i] = s_v[lane * 8 + i];
        dr[i] = s_dp[lane * 8 + i];
    }

    const __half* ep = g_ep_h + (size_t)b * THIST * AA;
    for (int i0 = 0; i0 < 64; i0 += 4) {
        int4 raw[4];
#pragma unroll
        for (int u = 0; u < 4; u++) {
            int t = w + (i0 + u) * 8;
            raw[u] = ldcs_int4(ep + (size_t)t * AA + lane * 8);
        }
        float ss[4];
#pragma unroll
        for (int u = 0; u < 4; u++) {
            const __half2* hp = (const __half2*)&raw[u];
            float acc = 0.f;
#pragma unroll
            for (int q = 0; q < 4; q++) {
                float2 f = __half22float2(hp[q]);
                acc = fmaf(vr[2 * q + 0], ftanh_fast(f.x + dr[2 * q + 0]), acc);
                acc = fmaf(vr[2 * q + 1], ftanh_fast(f.y + dr[2 * q + 1]), acc);
            }
            ss[u] = acc;
        }
#pragma unroll
        for (int off = 16; off; off >>= 1)
#pragma unroll
            for (int u = 0; u < 4; u++) ss[u] += __shfl_xor_sync(0xffffffffu, ss[u], off);
        if (lane == 0) {
#pragma unroll
            for (int u = 0; u < 4; u++) s_sc[w + (i0 + u) * 8] = ss[u];
        }
    }
    __syncthreads();

    float m = fmaxf(s_sc[tid], s_sc[tid + 256]);
#pragma unroll
    for (int off = 16; off; off >>= 1) m = fmaxf(m, __shfl_xor_sync(0xffffffffu, m, off));
    if (lane == 0) s_red[w] = m;
    __syncthreads();
    float mm = s_red[0];
#pragma unroll
    for (int i = 1; i < 8; i++) mm = fmaxf(mm, s_red[i]);
    float e0 = __expf(s_sc[tid] - mm);
    float e1 = __expf(s_sc[tid + 256] - mm);
    float sm = e0 + e1;
#pragma unroll
    for (int off = 16; off; off >>= 1) sm += __shfl_xor_sync(0xffffffffu, sm, off);
    __syncthreads();
    if (lane == 0) s_red[w] = sm;
    __syncthreads();
    float tot = s_red[0];
#pragma unroll
    for (int i = 1; i < 8; i++) tot += s_red[i];
    float inv = 1.f / tot;
    float p0 = e0 * inv, p1 = e1 * inv;
    s_sc[tid] = p0;
    s_sc[tid + 256] = p1;
    stcs_f(&attn_out[(size_t)b * THIST + tid], p0);
    stcs_f(&attn_out[(size_t)b * THIST + tid + 256], p1);
    __syncthreads();

    const __half* eob = g_eo_h + (size_t)b * THIST * HENC;
    float cacc[8];
#pragma unroll
    for (int q = 0; q < 8; q++) cacc[q] = 0.f;
    for (int i0 = 0; i0 < 64; i0 += 4) {
        int4 r[4];
        float p[4];
#pragma unroll
        for (int u = 0; u < 4; u++) {
            int t = w + (i0 + u) * 8;
            r[u] = ldcs_int4(eob + (size_t)t * HENC + lane * 8);
            p[u] = s_sc[t];
        }
#pragma unroll
        for (int u = 0; u < 4; u++) {
            const __half2* hp = (const __half2*)&r[u];
#pragma unroll
            for (int q = 0; q < 4; q++) {
                float2 f = __half22float2(hp[q]);
                cacc[2 * q + 0] = fmaf(p[u], f.x, cacc[2 * q + 0]);
                cacc[2 * q + 1] = fmaf(p[u], f.y, cacc[2 * q + 1]);
            }
        }
    }
#pragma unroll
    for (int q = 0; q < 8; q++) s_ctx[w][lane * 8 + q] = cacc[q];
    __syncthreads();

    const int e = tid;
    float csum = 0.f;
#pragma unroll
    for (int q = 0; q < 8; q++) csum += s_ctx[q][e];
    g_xcat0h[b * 512 + e] = __float2half(csum);
    g_xcat0h[b * 512 + 256 + e] = __float2half(g_h0[b * 256 + e]);
    g_xcatfch[b * 512 + 256 + e] = __float2half(csum);
}

// ---------------- double-buffered fp16 MMA 64x64 tile GEMM core, K-slab 64 ----------------
__device__ void gemm_mma_db(const __half* __restrict__ A, int lda,
                            const __half* __restrict__ B, int ldb,
                            int m0, int n0, int ktot, float cf[2][2][4]) {
    static __shared__ __half sA[2][64 * 72];
    static __shared__ __half sB[2][64 * 72];
    const int tid = threadIdx.x, lane = tid & 31, wid = tid >> 5;
    const int wm = wid & 1, wn = wid >> 1;
#pragma unroll
    for (int mt = 0; mt < 2; mt++)
#pragma unroll
        for (int nt = 0; nt < 2; nt++)
#pragma unroll
            for (int q = 0; q < 4; q++) cf[mt][nt][q] = 0.f;
    const int lrow = tid >> 2, lcol = (tid & 3) * 16;
    const uint32_t aBase = smem_u32(sA), bBase = smem_u32(sB);
    const int arow = wm * 32 + (lane & 15);
    const int acol8 = 8 * (lane >> 4);
    const int brow = wn * 16 + (lane & 7);
    const int bcol8 = 8 * ((lane >> 3) & 1);
    const int niter = ktot / 64;

    uint4 ra0 = *(const uint4*)&A[(size_t)(m0 + lrow) * lda + lcol];
    uint4 ra1 = *(const uint4*)&A[(size_t)(m0 + lrow) * lda + lcol + 8];
    uint4 rb0 = *(const uint4*)&B[(size_t)(n0 + lrow) * ldb + lcol];
    uint4 rb1 = *(const uint4*)&B[(size_t)(n0 + lrow) * ldb + lcol + 8];
    for (int it = 0; it < niter; it++) {
        const int buf = it & 1;
        *(uint4*)&sA[buf][lrow * 72 + lcol] = ra0;
        *(uint4*)&sA[buf][lrow * 72 + lcol + 8] = ra1;
        *(uint4*)&sB[buf][lrow * 72 + lcol] = rb0;
        *(uint4*)&sB[buf][lrow * 72 + lcol + 8] = rb1;
        __syncthreads();
        if (it + 1 < niter) {
            const int kc = (it + 1) * 64;
            ra0 = *(const uint4*)&A[(size_t)(m0 + lrow) * lda + kc + lcol];
            ra1 = *(const uint4*)&A[(size_t)(m0 + lrow) * lda + kc + lcol + 8];
            rb0 = *(const uint4*)&B[(size_t)(n0 + lrow) * ldb + kc + lcol];
            rb1 = *(const uint4*)&B[(size_t)(n0 + lrow) * ldb + kc + lcol + 8];
        }
        const uint32_t off = buf * (64 * 72) * 2;
#pragma unroll
        for (int ks = 0; ks < 64; ks += 16) {
            uint32_t a[2][4], bfrag[2][2];
#pragma unroll
            for (int mt = 0; mt < 2; mt++)
                ldsm_x4(aBase + off + ((arow + mt * 16) * 72 + ks + acol8) * 2,
                        a[mt][0], a[mt][1], a[mt][2], a[mt][3]);
#pragma unroll
            for (int nt = 0; nt < 2; nt++)
                ldsm_x2(bBase + off + ((brow + nt * 8) * 72 + ks + bcol8) * 2,
                        bfrag[nt][0], bfrag[nt][1]);
#pragma unroll
            for (int mt = 0; mt < 2; mt++)
#pragma unroll
                for (int nt = 0; nt < 2; nt++)
                    mma16816(cf[mt][nt], a[mt][0], a[mt][1], a[mt][2], a[mt][3],
                             bfrag[nt][0], bfrag[nt][1]);
        }
    }
}

// ---------------- fused recurrent step: 3 phases, 2 barriers ----------------
__global__ __launch_bounds__(256) void recurrent_step(const float* __restrict__ bfc1,
                                                      const float* __restrict__ Wfc2) {
    unsigned eps = 0;
    if (threadIdx.x == 0) eps = atomicAdd(&g_sense, 0);
    const int cta = blockIdx.x;
    const int tid = threadIdx.x;
    const int lane = tid & 31, wid = tid >> 5;
    const int wm = wid & 1, wn = wid >> 1;
    const int parity = lane & 1;
    float cf[2][2][4];

    // ===== P0: lstm0 gates GEMM + cell0 epilogue =====
    {
        const int m0 = (cta & 7) * 64, n0 = (cta >> 3) * 64;
        gemm_mma_db(g_xcat0h, 512, g_Wcat0rh, 512, m0, n0, 512, cf);
#pragma unroll
        for (int mt = 0; mt < 2; mt++)
#pragma unroll
            for (int nt = 0; nt < 2; nt++) {
                float t0 = __shfl_xor_sync(0xffffffffu, cf[mt][nt][0], 1);
                float t1 = __shfl_xor_sync(0xffffffffu, cf[mt][nt][1], 1);
                float t2 = __shfl_xor_sync(0xffffffffu, cf[mt][nt][2], 1);
                float t3 = __shfl_xor_sync(0xffffffffu, cf[mt][nt][3], 1);
                const int c = n0 + wn * 16 + (lane & 3) * 2 + nt * 8;
                const int j = c >> 2;
                const int r = m0 + wm * 32 + (lane >> 2) + mt * 16;
                int b;
                float gi, gf, gg, go;
                if (!parity) { b = r;     gi = cf[mt][nt][0]; gf = cf[mt][nt][1]; gg = t0; go = t1; }
                else         { b = r + 8; gi = t2;            gf = t3;            gg = cf[mt][nt][2]; go = cf[mt][nt][3]; }
                const float din = g_dec_in[b];
                const float4 wc = *(const float4*)&g_wcol0r[4 * j];
                const float4 bs = *(const float4*)&g_bias0r[4 * j];
                gi += din * wc.x + bs.x;
                gf += din * wc.y + bs.y;
                gg += din * wc.z + bs.z;
                go += din * wc.w + bs.w;
                const int idx = b * 256 + j;
                float cc = sig_precise(gf) * g_c0[idx] + sig_precise(gi) * tanhf(gg);
                float hh = sig_precise(go) * tanhf(cc);
                g_c0[idx] = cc;
                g_h0[idx] = hh;
                g_xcat1h[b * 512 + j] = __float2half(hh);
                g_xcat1h[b * 512 + 256 + j] = __float2half(g_h1[idx]);
            }
    }
    grid_barrier(&eps);

    // ===== P1: lstm1 gates GEMM + cell1 epilogue =====
    {
        const int m0 = (cta & 7) * 64, n0 = (cta >> 3) * 64;
        gemm_mma_db(g_xcat1h, 512, g_Wcat1rh, 512, m0, n0, 512, cf);
#pragma unroll
        for (int mt = 0; mt < 2; mt++)
#pragma unroll
            for (int nt = 0; nt < 2; nt++) {
                float t0 = __shfl_xor_sync(0xffffffffu, cf[mt][nt][0], 1);
                float t1 = __shfl_xor_sync(0xffffffffu, cf[mt][nt][1], 1);
                float t2 = __shfl_xor_sync(0xffffffffu, cf[mt][nt][2], 1);
                float t3 = __shfl_xor_sync(0xffffffffu, cf[mt][nt][3], 1);
                const int c = n0 + wn * 16 + (lane & 3) * 2 + nt * 8;
                const int j = c >> 2;
                const int r = m0 + wm * 32 + (lane >> 2) + mt * 16;
                int b;
                float gi, gf, gg, go;
                if (!parity) { b = r;     gi = cf[mt][nt][0]; gf = cf[mt][nt][1]; gg = t0; go = t1; }
                else         { b = r + 8; gi = t2;            gf = t3;            gg = cf[mt][nt][2]; go = cf[mt][nt][3]; }
                const float4 bs = *(const float4*)&g_bias1r[4 * j];
                gi += bs.x;
                gf += bs.y;
                gg += bs.z;
                go += bs.w;
                const int idx = b * 256 + j;
                float cc = sig_precise(gf) * g_c1[idx] + sig_precise(gi) * tanhf(gg);
                float hh = sig_precise(go) * tanhf(cc);
                g_c1[idx] = cc;
                g_h1[idx] = hh;
                g_xcatfch[b * 512 + j] = __float2half(hh);
            }
    }
    grid_barrier(&eps);

    // ===== P2: fc1+relu+Wfc2 partial (ctas 0-31) | dec_proj (ctas 32-63) =====
    if (cta < 32) {
        __shared__ float sfc[64][4];
        const int m0 = (cta & 7) * 64, n0 = (cta >> 3) * 64;
        gemm_mma_db(g_xcatfch, 512, g_Wfc1h, 512, m0, n0, 512, cf);
        float s0[2] = {0.f, 0.f}, s1[2] = {0.f, 0.f};
#pragma unroll
        for (int mt = 0; mt < 2; mt++)
#pragma unroll
            for (int nt = 0; nt < 2; nt++) {
                const int c = n0 + wn * 16 + (lane & 3) * 2 + nt * 8;
                const float b0 = bfc1[c], b1 = bfc1[c + 1];
                const float w0 = Wfc2[c], w1 = Wfc2[c + 1];
                s0[mt] += fmaxf(cf[mt][nt][0] + b0, 0.f) * w0 + fmaxf(cf[mt][nt][1] + b1, 0.f) * w1;
                s1[mt] += fmaxf(cf[mt][nt][2] + b0, 0.f) * w0 + fmaxf(cf[mt][nt][3] + b1, 0.f) * w1;
            }
#pragma unroll
        for (int off = 1; off < 4; off <<= 1) {
#pragma unroll
            for (int mt = 0; mt < 2; mt++) {
                s0[mt] += __shfl_xor_sync(0xffffffffu, s0[mt], off);
                s1[mt] += __shfl_xor_sync(0xffffffffu, s1[mt], off);
            }
        }
        if ((lane & 3) == 0) {
#pragma unroll
            for (int mt = 0; mt < 2; mt++) {
                int rl = wm * 32 + (lane >> 2) + mt * 16;
                sfc[rl][wn] = s0[mt];
                sfc[rl + 8][wn] = s1[mt];
            }
        }
        __syncthreads();
        if (tid < 64) {
            float p = sfc[tid][0] + sfc[tid][1] + sfc[tid][2] + sfc[tid][3];
            g_fcp4[(m0 + tid) * 4 + (cta >> 3)] = p;
        }
    } else if (cta < 64) {
        const int c2 = cta - 32;
        const int m0 = (c2 & 7) * 64, n0 = (c2 >> 3) * 64;
        gemm_mma_db(g_xcatfch, 512, g_Wt_dech, 256, m0, n0, 256, cf);
        const int erow = wm * 32 + (lane >> 2);
        const int ecol = wn * 16 + (lane & 3) * 2;
#pragma unroll
        for (int mt = 0; mt < 2; mt++)
#pragma unroll
            for (int nt = 0; nt < 2; nt++) {
                int r = m0 + erow + mt * 16, c = n0 + ecol + nt * 8;
                *(float2*)&g_dp[(size_t)r * AA + c] = make_float2(cf[mt][nt][0], cf[mt][nt][1]);
                *(float2*)&g_dp[(size_t)(r + 8) * AA + c] = make_float2(cf[mt][nt][2], cf[mt][nt][3]);
            }
    }
}

// ---------------- finalize last step's fc output ----------------
__global__ void finalize(const float* __restrict__ bfc2, float* __restrict__ outs) {
    int b = blockIdx.x * 256 + threadIdx.x;
    const float4 p = *(const float4*)&g_fcp4[b * 4];
    outs[b * TPRED + (TPRED - 1)] = (p.x + p.y) + (p.z + p.w) + bfc2[0];
}

// ---------------- initial dec_proj from encoder_hidden[1] ----------------
__global__ __launch_bounds__(256) void dp_init(const float* __restrict__ Wad) {
    __shared__ float sA[8][256];
    const int b0 = blockIdx.x * 8;
    const int tid = threadIdx.x;
#pragma unroll
    for (int q = 0; q < 2; q++) {
        int f4 = q * 256 + tid;
        int r = f4 >> 6, c = (f4 & 63) * 4;
        *(float4*)&sA[r][c] = *(const float4*)&g_h1[(size_t)(b0 + r) * 256 + c];
    }
    __syncthreads();
    float dpa[8];
#pragma unroll
    for (int r = 0; r < 8; r++) dpa[r] = 0.f;
#pragma unroll 4
    for (int h = 0; h < 256; h++) {
        const float wv = Wad[(size_t)h * AA + tid];
#pragma unroll
        for (int r = 0; r < 8; r++) dpa[r] = fmaf(sA[r][h], wv, dpa[r]);
    }
#pragma unroll
    for (int r = 0; r < 8; r++) g_dp[(b0 + r) * 256 + tid] = dpa[r];
}

// ---------------- host launcher ----------------
extern "C" void kernel_launch(void* const* d_in, const int* in_sizes, int n_in,
                              void* d_out, int out_size) {
    int off = (in_sizes[0] == 1) ? 1 : 0;
    const float* enc_out = (const float*)d_in[off + 0];
    const float* enc_h = (const float*)d_in[off + 1];
    const float* enc_c = (const float*)d_in[off + 2];
    const float* Wae = (const float*)d_in[off + 3];
    const float* Wad = (const float*)d_in[off + 4];
    const float* v = (const float*)d_in[off + 5];
    const float* Wih0 = (const float*)d_in[off + 6];
    const float* Whh0 = (const float*)d_in[off + 7];
    const float* bih0 = (const float*)d_in[off + 8];
    const float* bhh0 = (const float*)d_in[off + 9];
    const float* Wih1 = (const float*)d_in[off + 10];
    const float* Whh1 = (const float*)d_in[off + 11];
    const float* bih1 = (const float*)d_in[off + 12];
    const float* bhh1 = (const float*)d_in[off + 13];
    const float* Wfc1 = (const float*)d_in[off + 14];
    const float* bfc1 = (const float*)d_in[off + 15];
    const float* Wfc2 = (const float*)d_in[off + 16];
    const float* bfc2 = (const float*)d_in[off + 17];

    float* out = (float*)d_out;
    float* attn_base = out + (size_t)BB * TPRED;

    init_state<<<(BB * HH + 255) / 256, 256>>>(enc_h, enc_c);
    prep<<<2048, 256>>>(Wae, Wad, Wih0, Whh0, bih0, bhh0, Wih1, Whh1, bih1, bhh1, Wfc1);
    prep_eo<<<(BB * THIST * HENC / 4) / 256, 256>>>(enc_out);
    encproj_mma<<<dim3(4, 2048), 256>>>();
    dp_init<<<BB / 8, 256>>>(Wad);

    for (int s = 0; s < TPRED; s++) {
        attn_step<<<BB, 256>>>(v, attn_base + (size_t)s * BB * THIST, bfc2, out, s);
        recurrent_step<<<NCTAS, 256>>>(bfc1, Wfc2);
    }
    finalize<<<2, 256>>>(bfc2, out);
    (void)n_in;
    (void)out_size;
}